// round 1
// baseline (speedup 1.0000x reference)
#include <cuda_runtime.h>
#include <cuda_bf16.h>
#include <math.h>

// ---------------------------------------------------------------------------
// DGCNN discriminator, B=16, N=1024, K=20.
// Features stored point-major: [B, N, C]. All four edge-conv outputs are
// written directly into channel slices of g_cat [16,1024,512] (stride 512),
// making the concat free and letting every layer's input be a strided slice.
// ---------------------------------------------------------------------------

#define BB 16
#define NN 1024
#define KNNK 20
#define CATC 512

__device__ float g_G[BB * NN * NN];        // Gram / distance scratch (64 MB)
__device__ float g_cat[BB * NN * CATC];    // concat feature buffer  (32 MB)
__device__ float g_u[BB * NN * 256];       // W_a @ x_j per point
__device__ float g_v[BB * NN * 256];       // (W_b - W_a) @ x_i per point
__device__ float g_h[BB * NN * 1024];      // W4 output (64 MB)
__device__ float g_xx[BB * NN];
__device__ int   g_idx[BB * NN * KNNK];
__device__ float g_Wv[256 * 256];          // W_b - W_a scratch
__device__ float g_z[BB * 1088];           // [g | ye]
__device__ float g_ye0[BB * 16];
__device__ float g_z1[BB * 512];
__device__ float g_z2[BB * 256];

// ---------------------------------------------------------------------------
// Generic tiled GEMM: C[m,n] = sum_k A[m*lda+k] * W[n*ldw+k]  (A @ W^T)
// 32x32 tiles, 256 threads, 4 outputs/thread. Optional batching via z-dim.
// ---------------------------------------------------------------------------
#define TS 32
__global__ void gemm_nt(const float* __restrict__ A, const float* __restrict__ W,
                        float* __restrict__ C,
                        int M, int Ncols, int Kd,
                        int lda, int ldw, int ldc,
                        long batchA, long batchW, long batchC)
{
    int b = blockIdx.z;
    A += (long)b * batchA;
    W += (long)b * batchW;
    C += (long)b * batchC;

    __shared__ float As[TS][TS + 1];
    __shared__ float Ws[TS][TS + 1];

    int tid  = threadIdx.x;
    int tcol = tid & 31;
    int trow = tid >> 5;          // 0..7
    int row0 = blockIdx.y * TS;
    int col0 = blockIdx.x * TS;

    float acc[4] = {0.f, 0.f, 0.f, 0.f};

    for (int k0 = 0; k0 < Kd; k0 += TS) {
        #pragma unroll
        for (int i = 0; i < 4; i++) {
            int r  = trow + i * 8;
            int gk = k0 + tcol;
            int gr = row0 + r;
            As[r][tcol] = (gr < M && gk < Kd) ? A[(long)gr * lda + gk] : 0.f;
            int wr = col0 + r;
            Ws[r][tcol] = (wr < Ncols && gk < Kd) ? W[(long)wr * ldw + gk] : 0.f;
        }
        __syncthreads();
        #pragma unroll
        for (int k = 0; k < TS; k++) {
            float w = Ws[tcol][k];
            #pragma unroll
            for (int i = 0; i < 4; i++)
                acc[i] = fmaf(As[trow + i * 8][k], w, acc[i]);
        }
        __syncthreads();
    }

    #pragma unroll
    for (int i = 0; i < 4; i++) {
        int gr = row0 + trow + i * 8;
        int gc = col0 + tcol;
        if (gr < M && gc < Ncols) C[(long)gr * ldc + gc] = acc[i];
    }
}

// xx[p] = sum_c feat[p, c]^2
__global__ void xx_kernel(const float* __restrict__ feat, int lda, int d,
                          float* __restrict__ xx)
{
    int p = blockIdx.x * blockDim.x + threadIdx.x;
    if (p >= BB * NN) return;
    const float* r = feat + (long)p * lda;
    float s = 0.f;
    for (int c = 0; c < d; c++) s = fmaf(r[c], r[c], s);
    xx[p] = s;
}

// Per-row top-20 of pairwise = -xx_i - (-2*G_ij) - xx_j (largest first, ties
// broken by lower index, matching jax.lax.top_k).
__global__ void topk_kernel(const float* __restrict__ G,
                            const float* __restrict__ xx,
                            int* __restrict__ idx)
{
    int b = blockIdx.y, i = blockIdx.x;
    const float* Grow = G + ((long)b * NN + i) * NN;
    const float* xxb  = xx + b * NN;

    __shared__ float dist[NN];
    __shared__ float sval[256];
    __shared__ int   sidx[256];

    int t = threadIdx.x;
    float xi = xxb[i];
    for (int j = t; j < NN; j += 256) {
        float inner = -2.0f * Grow[j];
        dist[j] = -xi - inner - xxb[j];
    }
    __syncthreads();

    int* out = idx + ((long)b * NN + i) * KNNK;
    for (int kk = 0; kk < KNNK; kk++) {
        float bv = -__builtin_huge_valf();
        int   bi = 0x7fffffff;
        for (int j = t; j < NN; j += 256) {
            float v = dist[j];
            if (v > bv || (v == bv && j < bi)) { bv = v; bi = j; }
        }
        sval[t] = bv; sidx[t] = bi;
        __syncthreads();
        for (int s = 128; s > 0; s >>= 1) {
            if (t < s) {
                float ov = sval[t + s]; int oi = sidx[t + s];
                if (ov > sval[t] || (ov == sval[t] && oi < sidx[t])) {
                    sval[t] = ov; sidx[t] = oi;
                }
            }
            __syncthreads();
        }
        if (t == 0) {
            out[kk] = sidx[0];
            dist[sidx[0]] = -__builtin_huge_valf();
        }
        __syncthreads();
    }
}

// Wv = W[:, d:2d] - W[:, 0:d]
__global__ void wv_kernel(const float* __restrict__ W, float* __restrict__ Wv,
                          int outc, int d)
{
    int t = blockIdx.x * blockDim.x + threadIdx.x;
    if (t >= outc * d) return;
    int o = t / d, c = t - o * d;
    Wv[t] = W[(long)o * 2 * d + d + c] - W[(long)o * 2 * d + c];
}

// out[p, o] = max over k of lrelu(u[neighbor, o] + v[p, o]) -> cat slice
__global__ void gather_max_kernel(const float* __restrict__ u,
                                  const float* __restrict__ v,
                                  const int* __restrict__ idx,
                                  float* __restrict__ outp, int outc)
{
    int p = blockIdx.x;            // global point 0..16383
    int b = p >> 10;
    int o = threadIdx.x;
    if (o >= outc) return;
    float vi = v[(long)p * outc + o];
    const int* ip = idx + (long)p * KNNK;
    float m = -__builtin_huge_valf();
    #pragma unroll 4
    for (int kk = 0; kk < KNNK; kk++) {
        int j = ip[kk];
        float t = u[((long)(b << 10) + j) * outc + o] + vi;
        t = (t >= 0.f) ? t : 0.2f * t;
        m = fmaxf(m, t);
    }
    outp[(long)p * CATC + o] = m;
}

// z[b, o] = lrelu(max_n h[b, n, o])   (lrelu commutes with max)
__global__ void colmax_kernel(const float* __restrict__ h, float* __restrict__ z)
{
    int o = blockIdx.x * blockDim.x + threadIdx.x;   // 0..1023
    int b = blockIdx.y;
    const float* hb = h + (long)b * NN * 1024;
    float m = -__builtin_huge_valf();
    for (int n = 0; n < NN; n++) m = fmaxf(m, hb[(long)n * 1024 + o]);
    m = (m >= 0.f) ? m : 0.2f * m;
    z[b * 1088 + o] = m;
}

// Small FC: C[b,o] = (lrelu)(A[b,:] @ W[o,:] + bias[o])
__global__ void fc_kernel(const float* __restrict__ A, int lda,
                          const float* __restrict__ W,
                          const float* __restrict__ bias,
                          float* __restrict__ C, int ldc,
                          int Bn, int O, int Kd, int relu)
{
    int t = blockIdx.x * blockDim.x + threadIdx.x;
    if (t >= Bn * O) return;
    int b = t / O, o = t - b * O;
    const float* a = A + (long)b * lda;
    const float* w = W + (long)o * Kd;
    float s = bias ? bias[o] : 0.f;
    for (int k = 0; k < Kd; k++) s = fmaf(a[k], w[k], s);
    if (relu) s = (s >= 0.f) ? s : 0.2f * s;
    C[(long)b * ldc + o] = s;
}

// ---------------------------------------------------------------------------
static void run_layer(const float* feat, int lda, int d, int outc,
                      const float* W, float* catOut,
                      float* G, float* xx, int* idxp, float* Wv,
                      float* u, float* v)
{
    xx_kernel<<<(BB * NN + 255) / 256, 256>>>(feat, lda, d, xx);

    dim3 gG(NN / TS, NN / TS, BB);
    gemm_nt<<<gG, 256>>>(feat, feat, G, NN, NN, d, lda, lda, NN,
                         (long)NN * lda, (long)NN * lda, (long)NN * NN);

    topk_kernel<<<dim3(NN, BB), 256>>>(G, xx, idxp);

    int nwv = outc * d;
    wv_kernel<<<(nwv + 255) / 256, 256>>>(W, Wv, outc, d);

    dim3 gu((outc + TS - 1) / TS, (BB * NN) / TS, 1);
    gemm_nt<<<gu, 256>>>(feat, W,  u, BB * NN, outc, d, lda, 2 * d, outc, 0, 0, 0);
    gemm_nt<<<gu, 256>>>(feat, Wv, v, BB * NN, outc, d, lda, d,     outc, 0, 0, 0);

    gather_max_kernel<<<BB * NN, outc>>>(u, v, idxp, catOut, outc);
}

extern "C" void kernel_launch(void* const* d_in, const int* in_sizes, int n_in,
                              void* d_out, int out_size)
{
    const float* x   = (const float*)d_in[0];
    const float* y   = (const float*)d_in[1];
    const float* W0  = (const float*)d_in[2];
    const float* W1  = (const float*)d_in[3];
    const float* W2  = (const float*)d_in[4];
    const float* W3  = (const float*)d_in[5];
    const float* W4  = (const float*)d_in[6];
    const float* L0  = (const float*)d_in[7];
    const float* L1  = (const float*)d_in[8];
    const float* L2w = (const float*)d_in[9];
    const float* L2b = (const float*)d_in[10];
    const float* F0w = (const float*)d_in[11];
    const float* F0b = (const float*)d_in[12];
    const float* F1w = (const float*)d_in[13];
    const float* F1b = (const float*)d_in[14];
    float* out = (float*)d_out;

    float *G, *cat, *u, *v, *h, *xx, *Wv, *z, *ye0, *z1, *z2;
    int* idxp;
    cudaGetSymbolAddress((void**)&G,    g_G);
    cudaGetSymbolAddress((void**)&cat,  g_cat);
    cudaGetSymbolAddress((void**)&u,    g_u);
    cudaGetSymbolAddress((void**)&v,    g_v);
    cudaGetSymbolAddress((void**)&h,    g_h);
    cudaGetSymbolAddress((void**)&xx,   g_xx);
    cudaGetSymbolAddress((void**)&Wv,   g_Wv);
    cudaGetSymbolAddress((void**)&z,    g_z);
    cudaGetSymbolAddress((void**)&ye0,  g_ye0);
    cudaGetSymbolAddress((void**)&z1,   g_z1);
    cudaGetSymbolAddress((void**)&z2,   g_z2);
    cudaGetSymbolAddress((void**)&idxp, g_idx);

    // Four edge-conv layers, outputs into cat channel slices 0/64/128/256.
    run_layer(x,         6,   6,   64,  W0, cat + 0,   G, xx, idxp, Wv, u, v);
    run_layer(cat + 0,   512, 64,  64,  W1, cat + 64,  G, xx, idxp, Wv, u, v);
    run_layer(cat + 64,  512, 64,  128, W2, cat + 128, G, xx, idxp, Wv, u, v);
    run_layer(cat + 128, 512, 128, 256, W3, cat + 256, G, xx, idxp, Wv, u, v);

    // h = cat @ W4^T  [16384, 1024], then g = lrelu(max_n h) -> z[:, 0:1024]
    dim3 g4(1024 / TS, (BB * NN) / TS, 1);
    gemm_nt<<<g4, 256>>>(cat, W4, h, BB * NN, 1024, 512, 512, 512, 1024, 0, 0, 0);
    colmax_kernel<<<dim3(4, BB), 256>>>(h, z);

    // y path -> z[:, 1024:1088]
    fc_kernel<<<1, 256>>>(y, 16, F0w, F0b, ye0, 16, BB, 16, 16, 1);
    fc_kernel<<<(BB * 64 + 255) / 256, 256>>>(ye0, 16, F1w, F1b, z + 1024, 1088,
                                              BB, 64, 16, 1);

    // Final MLP
    fc_kernel<<<(BB * 512 + 255) / 256, 256>>>(z, 1088, L0, nullptr, z1, 512,
                                               BB, 512, 1088, 1);
    fc_kernel<<<(BB * 256 + 255) / 256, 256>>>(z1, 512, L1, nullptr, z2, 256,
                                               BB, 256, 512, 1);
    fc_kernel<<<1, 16>>>(z2, 256, L2w, L2b, out, 1, BB, 1, 256, 0);
}

// round 2
// speedup vs baseline: 1.5779x; 1.5779x over previous
#include <cuda_runtime.h>
#include <cuda_bf16.h>
#include <math.h>

// ---------------------------------------------------------------------------
// DGCNN discriminator, B=16, N=1024, K=20  (round 2: register-tiled GEMM,
// fused u/v GEMM, register-resident top-k).
// ---------------------------------------------------------------------------

#define BB 16
#define NN 1024
#define KNNK 20
#define CATC 512

__device__ float g_G[BB * NN * NN];        // Gram scratch
__device__ float g_cat[BB * NN * CATC];    // concat feature buffer
__device__ float g_uv[BB * NN * 512];      // [u | v] per point (2*outc <= 512)
__device__ float g_h[BB * NN * 1024];      // W4 output
__device__ float g_xx[BB * NN];
__device__ int   g_idx[BB * NN * KNNK];
__device__ float g_Wuv[512 * 256];         // stacked [W_a ; W_b - W_a]
__device__ float g_z[BB * 1088];
__device__ float g_ye0[BB * 16];
__device__ float g_z1[BB * 512];
__device__ float g_z2[BB * 256];

// ---------------------------------------------------------------------------
// Register-tiled GEMM: C = A @ W^T.  Block 128x64, 256 threads, 8x4 per
// thread, BK=16.  Requires M % 128 == 0 and Ncols % 64 == 0 (true for all
// call sites).  K is guarded (zero fill).
// ---------------------------------------------------------------------------
#define BM 128
#define BN 64
#define BK 16

__global__ __launch_bounds__(256, 4)
void gemm_nt(const float* __restrict__ A, const float* __restrict__ W,
             float* __restrict__ C,
             int Kd, int lda, int ldw, int ldc,
             long batchA, long batchW, long batchC)
{
    int b = blockIdx.z;
    A += (long)b * batchA;
    W += (long)b * batchW;
    C += (long)b * batchC;

    __shared__ float As[BK][BM + 4];   // row stride 132 floats (16B aligned)
    __shared__ float Ws[BK][BN + 4];   // row stride 68 floats  (16B aligned)

    int tid = threadIdx.x;
    int tx  = tid & 15;          // n-group: cols tx*4 .. tx*4+3
    int ty  = tid >> 4;          // m-group: rows ty*8 .. ty*8+7
    int row0 = blockIdx.y * BM;
    int col0 = blockIdx.x * BN;

    float acc[8][4];
    #pragma unroll
    for (int i = 0; i < 8; i++)
        #pragma unroll
        for (int j = 0; j < 4; j++) acc[i][j] = 0.f;

    for (int k0 = 0; k0 < Kd; k0 += BK) {
        // load A tile [BM][BK] -> As[kk][m]
        #pragma unroll
        for (int i = 0; i < 8; i++) {
            int id = tid + i * 256;
            int kk = id & 15, m = id >> 4;
            int gk = k0 + kk;
            As[kk][m] = (gk < Kd) ? A[(long)(row0 + m) * lda + gk] : 0.f;
        }
        // load W tile [BN][BK] -> Ws[kk][n]
        #pragma unroll
        for (int i = 0; i < 4; i++) {
            int id = tid + i * 256;
            int kk = id & 15, n = id >> 4;
            int gk = k0 + kk;
            Ws[kk][n] = (gk < Kd) ? W[(long)(col0 + n) * ldw + gk] : 0.f;
        }
        __syncthreads();

        #pragma unroll
        for (int kk = 0; kk < BK; kk++) {
            float4 b4 = *(const float4*)&Ws[kk][tx * 4];
            float4 a0 = *(const float4*)&As[kk][ty * 8];
            float4 a1 = *(const float4*)&As[kk][ty * 8 + 4];
            float av[8] = {a0.x, a0.y, a0.z, a0.w, a1.x, a1.y, a1.z, a1.w};
            float bv[4] = {b4.x, b4.y, b4.z, b4.w};
            #pragma unroll
            for (int i = 0; i < 8; i++)
                #pragma unroll
                for (int j = 0; j < 4; j++)
                    acc[i][j] = fmaf(av[i], bv[j], acc[i][j]);
        }
        __syncthreads();
    }

    #pragma unroll
    for (int i = 0; i < 8; i++) {
        float4 v = make_float4(acc[i][0], acc[i][1], acc[i][2], acc[i][3]);
        *(float4*)&C[(long)(row0 + ty * 8 + i) * ldc + col0 + tx * 4] = v;
    }
}

// xx[p] = sum_c feat[p, c]^2
__global__ void xx_kernel(const float* __restrict__ feat, int lda, int d,
                          float* __restrict__ xx)
{
    int p = blockIdx.x * blockDim.x + threadIdx.x;
    if (p >= BB * NN) return;
    const float* r = feat + (long)p * lda;
    float s = 0.f;
    for (int c = 0; c < d; c++) s = fmaf(r[c], r[c], s);
    xx[p] = s;
}

// ---------------------------------------------------------------------------
// Register-resident top-20.  256 threads, 4 distances/thread in registers.
// 64-bit packed key: (ordered-float << 32) | (0xFFFFFFFF - j) so max-key =
// (max value, min index) — exact jax.lax.top_k tie-break.
// ---------------------------------------------------------------------------
__device__ __forceinline__ unsigned int ord_float(float v) {
    unsigned int u = __float_as_uint(v);
    return (u & 0x80000000u) ? ~u : (u | 0x80000000u);
}

__global__ __launch_bounds__(256)
void topk_kernel(const float* __restrict__ G, const float* __restrict__ xx,
                 int* __restrict__ idx)
{
    int b = blockIdx.y, i = blockIdx.x;
    const float* Grow = G + ((long)b * NN + i) * NN;
    const float* xxb  = xx + b * NN;
    int t = threadIdx.x;
    int lane = t & 31, warp = t >> 5;

    __shared__ unsigned long long wkey[8];

    float xi = xxb[i];
    int j0 = t * 4;
    float4 g4  = *(const float4*)&Grow[j0];
    float4 xx4 = *(const float4*)&xxb[j0];

    unsigned long long key[4];
    {
        float gg[4] = {g4.x, g4.y, g4.z, g4.w};
        float xj[4] = {xx4.x, xx4.y, xx4.z, xx4.w};
        #pragma unroll
        for (int q = 0; q < 4; q++) {
            float inner = -2.0f * gg[q];
            float v = -xi - inner - xj[q];
            key[q] = ((unsigned long long)ord_float(v) << 32)
                   | (unsigned int)(0xFFFFFFFFu - (unsigned int)(j0 + q));
        }
    }

    int* out = idx + ((long)b * NN + i) * KNNK;

    for (int kk = 0; kk < KNNK; kk++) {
        unsigned long long best = key[0];
        #pragma unroll
        for (int q = 1; q < 4; q++) best = max(best, key[q]);
        #pragma unroll
        for (int s = 16; s > 0; s >>= 1)
            best = max(best, __shfl_xor_sync(0xFFFFFFFFu, best, s));
        if (lane == 0) wkey[warp] = best;
        __syncthreads();
        unsigned long long win = wkey[0];
        #pragma unroll
        for (int w = 1; w < 8; w++) win = max(win, wkey[w]);
        int wj = (int)(0xFFFFFFFFu - (unsigned int)(win & 0xFFFFFFFFu));
        if (t == 0) out[kk] = wj;
        // invalidate winner (owned by exactly one thread)
        #pragma unroll
        for (int q = 0; q < 4; q++)
            if (key[q] == win) key[q] = 0ull;
        __syncthreads();
    }
}

// Wuv: rows [0, outc) = W[:, 0:d];  rows [outc, 2*outc) = W[:, d:2d] - W[:, 0:d]
__global__ void wuv_kernel(const float* __restrict__ W, float* __restrict__ Wuv,
                           int outc, int d)
{
    int t = blockIdx.x * blockDim.x + threadIdx.x;
    if (t >= 2 * outc * d) return;
    int r = t / d, c = t - r * d;
    if (r < outc) Wuv[t] = W[(long)r * 2 * d + c];
    else {
        int o = r - outc;
        Wuv[t] = W[(long)o * 2 * d + d + c] - W[(long)o * 2 * d + c];
    }
}

// out[p, o] = max_k lrelu(u[nbr, o] + v[p, o]);  uv layout [p][2*outc]
__global__ void gather_max_kernel(const float* __restrict__ uv,
                                  const int* __restrict__ idx,
                                  float* __restrict__ outp, int outc)
{
    int p = blockIdx.x;
    int b = p >> 10;
    int o = threadIdx.x;
    if (o >= outc) return;
    int ldu = 2 * outc;
    float vi = uv[(long)p * ldu + outc + o];
    const int* ip = idx + (long)p * KNNK;
    float m = -__builtin_huge_valf();
    #pragma unroll 4
    for (int kk = 0; kk < KNNK; kk++) {
        int j = ip[kk];
        float t = uv[((long)(b << 10) + j) * ldu + o] + vi;
        t = (t >= 0.f) ? t : 0.2f * t;
        m = fmaxf(m, t);
    }
    outp[(long)p * CATC + o] = m;
}

// z[b, o] = lrelu(max_n h[b, n, o])
__global__ void colmax_kernel(const float* __restrict__ h, float* __restrict__ z)
{
    int o = blockIdx.x * blockDim.x + threadIdx.x;
    int b = blockIdx.y;
    const float* hb = h + (long)b * NN * 1024;
    float m = -__builtin_huge_valf();
    #pragma unroll 8
    for (int n = 0; n < NN; n++) m = fmaxf(m, hb[(long)n * 1024 + o]);
    m = (m >= 0.f) ? m : 0.2f * m;
    z[b * 1088 + o] = m;
}

// Small FC: C[b,o] = (lrelu)(A[b,:] @ W[o,:] + bias[o])
__global__ void fc_kernel(const float* __restrict__ A, int lda,
                          const float* __restrict__ W,
                          const float* __restrict__ bias,
                          float* __restrict__ C, int ldc,
                          int Bn, int O, int Kd, int relu)
{
    int t = blockIdx.x * blockDim.x + threadIdx.x;
    if (t >= Bn * O) return;
    int b = t / O, o = t - b * O;
    const float* a = A + (long)b * lda;
    const float* w = W + (long)o * Kd;
    float s0 = 0.f, s1 = 0.f, s2 = 0.f, s3 = 0.f;
    int k = 0;
    for (; k + 3 < Kd; k += 4) {
        s0 = fmaf(a[k],     w[k],     s0);
        s1 = fmaf(a[k + 1], w[k + 1], s1);
        s2 = fmaf(a[k + 2], w[k + 2], s2);
        s3 = fmaf(a[k + 3], w[k + 3], s3);
    }
    for (; k < Kd; k++) s0 = fmaf(a[k], w[k], s0);
    float s = (s0 + s1) + (s2 + s3) + (bias ? bias[o] : 0.f);
    if (relu) s = (s >= 0.f) ? s : 0.2f * s;
    C[(long)b * ldc + o] = s;
}

// ---------------------------------------------------------------------------
static void run_layer(const float* feat, int lda, int d, int outc,
                      const float* W, float* catOut,
                      float* G, float* xx, int* idxp, float* Wuv, float* uv)
{
    xx_kernel<<<(BB * NN + 255) / 256, 256>>>(feat, lda, d, xx);

    dim3 gG(NN / BN, NN / BM, BB);
    gemm_nt<<<gG, 256>>>(feat, feat, G, d, lda, lda, NN,
                         (long)NN * lda, (long)NN * lda, (long)NN * NN);

    topk_kernel<<<dim3(NN, BB), 256>>>(G, xx, idxp);

    int nw = 2 * outc * d;
    wuv_kernel<<<(nw + 255) / 256, 256>>>(W, Wuv, outc, d);

    dim3 gu((2 * outc) / BN, (BB * NN) / BM, 1);
    gemm_nt<<<gu, 256>>>(feat, Wuv, uv, d, lda, d, 2 * outc, 0, 0, 0);

    gather_max_kernel<<<BB * NN, outc>>>(uv, idxp, catOut, outc);
}

extern "C" void kernel_launch(void* const* d_in, const int* in_sizes, int n_in,
                              void* d_out, int out_size)
{
    const float* x   = (const float*)d_in[0];
    const float* y   = (const float*)d_in[1];
    const float* W0  = (const float*)d_in[2];
    const float* W1  = (const float*)d_in[3];
    const float* W2  = (const float*)d_in[4];
    const float* W3  = (const float*)d_in[5];
    const float* W4  = (const float*)d_in[6];
    const float* L0  = (const float*)d_in[7];
    const float* L1  = (const float*)d_in[8];
    const float* L2w = (const float*)d_in[9];
    const float* L2b = (const float*)d_in[10];
    const float* F0w = (const float*)d_in[11];
    const float* F0b = (const float*)d_in[12];
    const float* F1w = (const float*)d_in[13];
    const float* F1b = (const float*)d_in[14];
    float* out = (float*)d_out;

    float *G, *cat, *uv, *h, *xx, *Wuv, *z, *ye0, *z1, *z2;
    int* idxp;
    cudaGetSymbolAddress((void**)&G,    g_G);
    cudaGetSymbolAddress((void**)&cat,  g_cat);
    cudaGetSymbolAddress((void**)&uv,   g_uv);
    cudaGetSymbolAddress((void**)&h,    g_h);
    cudaGetSymbolAddress((void**)&xx,   g_xx);
    cudaGetSymbolAddress((void**)&Wuv,  g_Wuv);
    cudaGetSymbolAddress((void**)&z,    g_z);
    cudaGetSymbolAddress((void**)&ye0,  g_ye0);
    cudaGetSymbolAddress((void**)&z1,   g_z1);
    cudaGetSymbolAddress((void**)&z2,   g_z2);
    cudaGetSymbolAddress((void**)&idxp, g_idx);

    run_layer(x,         6,   6,   64,  W0, cat + 0,   G, xx, idxp, Wuv, uv);
    run_layer(cat + 0,   512, 64,  64,  W1, cat + 64,  G, xx, idxp, Wuv, uv);
    run_layer(cat + 64,  512, 64,  128, W2, cat + 128, G, xx, idxp, Wuv, uv);
    run_layer(cat + 128, 512, 128, 256, W3, cat + 256, G, xx, idxp, Wuv, uv);

    dim3 g4(1024 / BN, (BB * NN) / BM, 1);
    gemm_nt<<<g4, 256>>>(cat, W4, h, 512, 512, 512, 1024, 0, 0, 0);
    colmax_kernel<<<dim3(4, BB), 256>>>(h, z);

    fc_kernel<<<1, 256>>>(y, 16, F0w, F0b, ye0, 16, BB, 16, 16, 1);
    fc_kernel<<<(BB * 64 + 255) / 256, 256>>>(ye0, 16, F1w, F1b, z + 1024, 1088,
                                              BB, 64, 16, 1);

    fc_kernel<<<(BB * 512 + 255) / 256, 256>>>(z, 1088, L0, nullptr, z1, 512,
                                               BB, 512, 1088, 1);
    fc_kernel<<<(BB * 256 + 255) / 256, 256>>>(z1, 512, L1, nullptr, z2, 256,
                                               BB, 256, 512, 1);
    fc_kernel<<<1, 16>>>(z2, 256, L2w, L2b, out, 1, BB, 1, 256, 0);
}

// round 3
// speedup vs baseline: 1.6201x; 1.0267x over previous
#include <cuda_runtime.h>
#include <cuda_bf16.h>
#include <math.h>

// ---------------------------------------------------------------------------
// DGCNN discriminator, B=16, N=1024, K=20.
// Round 3: 128x128 double-buffered register-tiled GEMM (8x8/thread, BK=8),
// W4 GEMM fused with the global column-max (no h buffer).
// ---------------------------------------------------------------------------

#define BB 16
#define NN 1024
#define KNNK 20
#define CATC 512

__device__ float g_G[BB * NN * NN];
__device__ float g_cat[BB * NN * CATC];
__device__ float g_uv[BB * NN * 512];
__device__ float g_xx[BB * NN];
__device__ int   g_idx[BB * NN * KNNK];
__device__ float g_Wuv[512 * 256];
__device__ unsigned int g_zenc[BB * 1024];
__device__ float g_z[BB * 1088];
__device__ float g_ye0[BB * 16];
__device__ float g_z1[BB * 512];
__device__ float g_z2[BB * 256];

__device__ __forceinline__ unsigned int ord_float(float v) {
    unsigned int u = __float_as_uint(v);
    return (u & 0x80000000u) ? ~u : (u | 0x80000000u);
}
__device__ __forceinline__ float ord_decode(unsigned int e) {
    unsigned int u = (e & 0x80000000u) ? (e ^ 0x80000000u) : ~e;
    return __uint_as_float(u);
}

// ---------------------------------------------------------------------------
// C = A @ W^T.  Block 128x128, 256 threads, 8x8 acc, BK=8, double buffered.
// Requires M % 128 == 0, Ncols % 128 == 0.  K guarded (zero fill).
// EPI==0: store C.  EPI==1: skip C, atomicMax ord-encoded column max into
// zenc[batchRow * 1024 + col]   (batchRow = row0 >> 10; rows per batch 1024).
// ---------------------------------------------------------------------------
#define BM 128
#define BN 128
#define BK 8

template<int EPI>
__global__ __launch_bounds__(256, 2)
void gemm_nt(const float* __restrict__ A, const float* __restrict__ W,
             float* __restrict__ C, unsigned int* __restrict__ zenc,
             int Kd, int lda, int ldw, int ldc,
             long batchA, long batchW, long batchC)
{
    int bz = blockIdx.z;
    A += (long)bz * batchA;
    W += (long)bz * batchW;
    C += (long)bz * batchC;

    __shared__ float As[2][BK][BM + 4];
    __shared__ float Ws[2][BK][BN + 4];
    __shared__ float red[16][BN];      // only used when EPI==1

    int tid = threadIdx.x;
    int tx  = tid & 15;                // 8 cols each
    int ty  = tid >> 4;                // 8 rows each
    int row0 = blockIdx.y * BM;
    int col0 = blockIdx.x * BN;

    int lm = tid >> 1;                 // 0..127 (row of A tile / col of W tile)
    int ks = (tid & 1) * 4;            // k sub-offset 0 or 4

    const bool vecA = ((lda & 3) == 0) && ((Kd & 7) == 0);
    const bool vecW = ((ldw & 3) == 0) && ((Kd & 7) == 0);
    const float* Arow = A + (long)(row0 + lm) * lda;
    const float* Wrow = W + (long)(col0 + lm) * ldw;

    float acc[8][8];
    #pragma unroll
    for (int i = 0; i < 8; i++)
        #pragma unroll
        for (int j = 0; j < 8; j++) acc[i][j] = 0.f;

    float4 ra, rw;

    // ---- load tile 0 ----
    if (vecA) ra = *(const float4*)(Arow + ks);
    else {
        float t[4];
        #pragma unroll
        for (int q = 0; q < 4; q++) { int gk = ks + q; t[q] = (gk < Kd) ? Arow[gk] : 0.f; }
        ra = make_float4(t[0], t[1], t[2], t[3]);
    }
    if (vecW) rw = *(const float4*)(Wrow + ks);
    else {
        float t[4];
        #pragma unroll
        for (int q = 0; q < 4; q++) { int gk = ks + q; t[q] = (gk < Kd) ? Wrow[gk] : 0.f; }
        rw = make_float4(t[0], t[1], t[2], t[3]);
    }
    As[0][ks + 0][lm] = ra.x; As[0][ks + 1][lm] = ra.y;
    As[0][ks + 2][lm] = ra.z; As[0][ks + 3][lm] = ra.w;
    Ws[0][ks + 0][lm] = rw.x; Ws[0][ks + 1][lm] = rw.y;
    Ws[0][ks + 2][lm] = rw.z; Ws[0][ks + 3][lm] = rw.w;
    __syncthreads();

    int buf = 0;
    for (int k0 = 0; k0 < Kd; k0 += BK) {
        int knext = k0 + BK;
        bool more = knext < Kd;
        if (more) {
            if (vecA) ra = *(const float4*)(Arow + knext + ks);
            else {
                float t[4];
                #pragma unroll
                for (int q = 0; q < 4; q++) { int gk = knext + ks + q; t[q] = (gk < Kd) ? Arow[gk] : 0.f; }
                ra = make_float4(t[0], t[1], t[2], t[3]);
            }
            if (vecW) rw = *(const float4*)(Wrow + knext + ks);
            else {
                float t[4];
                #pragma unroll
                for (int q = 0; q < 4; q++) { int gk = knext + ks + q; t[q] = (gk < Kd) ? Wrow[gk] : 0.f; }
                rw = make_float4(t[0], t[1], t[2], t[3]);
            }
        }

        #pragma unroll
        for (int kk = 0; kk < BK; kk++) {
            float4 a0 = *(const float4*)&As[buf][kk][ty * 8];
            float4 a1 = *(const float4*)&As[buf][kk][ty * 8 + 4];
            float4 b0 = *(const float4*)&Ws[buf][kk][tx * 8];
            float4 b1 = *(const float4*)&Ws[buf][kk][tx * 8 + 4];
            float av[8] = {a0.x, a0.y, a0.z, a0.w, a1.x, a1.y, a1.z, a1.w};
            float bv[8] = {b0.x, b0.y, b0.z, b0.w, b1.x, b1.y, b1.z, b1.w};
            #pragma unroll
            for (int i = 0; i < 8; i++)
                #pragma unroll
                for (int j = 0; j < 8; j++)
                    acc[i][j] = fmaf(av[i], bv[j], acc[i][j]);
        }

        if (more) {
            int nb = buf ^ 1;
            As[nb][ks + 0][lm] = ra.x; As[nb][ks + 1][lm] = ra.y;
            As[nb][ks + 2][lm] = ra.z; As[nb][ks + 3][lm] = ra.w;
            Ws[nb][ks + 0][lm] = rw.x; Ws[nb][ks + 1][lm] = rw.y;
            Ws[nb][ks + 2][lm] = rw.z; Ws[nb][ks + 3][lm] = rw.w;
            __syncthreads();
            buf = nb;
        }
    }

    if (EPI == 0) {
        #pragma unroll
        for (int i = 0; i < 8; i++) {
            float* cr = C + (long)(row0 + ty * 8 + i) * ldc + col0 + tx * 8;
            *(float4*)cr       = make_float4(acc[i][0], acc[i][1], acc[i][2], acc[i][3]);
            *(float4*)(cr + 4) = make_float4(acc[i][4], acc[i][5], acc[i][6], acc[i][7]);
        }
    } else {
        // column max over this block's 128 rows
        #pragma unroll
        for (int j = 0; j < 8; j++) {
            float m = acc[0][j];
            #pragma unroll
            for (int i = 1; i < 8; i++) m = fmaxf(m, acc[i][j]);
            red[ty][tx * 8 + j] = m;
        }
        __syncthreads();
        if (tid < BN) {
            float m = red[0][tid];
            #pragma unroll
            for (int r = 1; r < 16; r++) m = fmaxf(m, red[r][tid]);
            int b = row0 >> 10;
            atomicMax(&zenc[b * 1024 + col0 + tid], ord_float(m));
        }
    }
}

// xx[p] = sum_c feat[p, c]^2
__global__ void xx_kernel(const float* __restrict__ feat, int lda, int d,
                          float* __restrict__ xx)
{
    int p = blockIdx.x * blockDim.x + threadIdx.x;
    if (p >= BB * NN) return;
    const float* r = feat + (long)p * lda;
    float s = 0.f;
    for (int c = 0; c < d; c++) s = fmaf(r[c], r[c], s);
    xx[p] = s;
}

// Register-resident top-20 with exact jax tie-break.
__global__ __launch_bounds__(256)
void topk_kernel(const float* __restrict__ G, const float* __restrict__ xx,
                 int* __restrict__ idx)
{
    int b = blockIdx.y, i = blockIdx.x;
    const float* Grow = G + ((long)b * NN + i) * NN;
    const float* xxb  = xx + b * NN;
    int t = threadIdx.x;
    int lane = t & 31, warp = t >> 5;

    __shared__ unsigned long long wkey[8];

    float xi = xxb[i];
    int j0 = t * 4;
    float4 g4  = *(const float4*)&Grow[j0];
    float4 xx4 = *(const float4*)&xxb[j0];

    unsigned long long key[4];
    {
        float gg[4] = {g4.x, g4.y, g4.z, g4.w};
        float xj[4] = {xx4.x, xx4.y, xx4.z, xx4.w};
        #pragma unroll
        for (int q = 0; q < 4; q++) {
            float inner = -2.0f * gg[q];
            float v = -xi - inner - xj[q];
            key[q] = ((unsigned long long)ord_float(v) << 32)
                   | (unsigned int)(0xFFFFFFFFu - (unsigned int)(j0 + q));
        }
    }

    int* out = idx + ((long)b * NN + i) * KNNK;

    for (int kk = 0; kk < KNNK; kk++) {
        unsigned long long best = key[0];
        #pragma unroll
        for (int q = 1; q < 4; q++) best = max(best, key[q]);
        #pragma unroll
        for (int s = 16; s > 0; s >>= 1)
            best = max(best, __shfl_xor_sync(0xFFFFFFFFu, best, s));
        if (lane == 0) wkey[warp] = best;
        __syncthreads();
        unsigned long long win = wkey[0];
        #pragma unroll
        for (int w = 1; w < 8; w++) win = max(win, wkey[w]);
        int wj = (int)(0xFFFFFFFFu - (unsigned int)(win & 0xFFFFFFFFu));
        if (t == 0) out[kk] = wj;
        #pragma unroll
        for (int q = 0; q < 4; q++)
            if (key[q] == win) key[q] = 0ull;
        __syncthreads();
    }
}

// Wuv: rows [0,outc) = W[:,0:d];  rows [outc,2outc) = W[:,d:2d]-W[:,0:d]
__global__ void wuv_kernel(const float* __restrict__ W, float* __restrict__ Wuv,
                           int outc, int d)
{
    int t = blockIdx.x * blockDim.x + threadIdx.x;
    if (t >= 2 * outc * d) return;
    int r = t / d, c = t - r * d;
    if (r < outc) Wuv[t] = W[(long)r * 2 * d + c];
    else {
        int o = r - outc;
        Wuv[t] = W[(long)o * 2 * d + d + c] - W[(long)o * 2 * d + c];
    }
}

// out[p, o] = max_k lrelu(u[nbr, o] + v[p, o])
__global__ void gather_max_kernel(const float* __restrict__ uv,
                                  const int* __restrict__ idx,
                                  float* __restrict__ outp, int outc)
{
    int p = blockIdx.x;
    int b = p >> 10;
    int o = threadIdx.x;
    if (o >= outc) return;
    int ldu = 2 * outc;
    float vi = uv[(long)p * ldu + outc + o];
    const int* ip = idx + (long)p * KNNK;
    float m = -__builtin_huge_valf();
    #pragma unroll 4
    for (int kk = 0; kk < KNNK; kk++) {
        int j = ip[kk];
        float t = uv[((long)(b << 10) + j) * ldu + o] + vi;
        t = (t >= 0.f) ? t : 0.2f * t;
        m = fmaxf(m, t);
    }
    outp[(long)p * CATC + o] = m;
}

__global__ void zenc_init_kernel(unsigned int* __restrict__ zenc)
{
    int t = blockIdx.x * blockDim.x + threadIdx.x;
    if (t < BB * 1024) zenc[t] = 0u;
}

__global__ void zenc_decode_kernel(const unsigned int* __restrict__ zenc,
                                   float* __restrict__ z)
{
    int t = blockIdx.x * blockDim.x + threadIdx.x;
    if (t >= BB * 1024) return;
    int b = t >> 10, o = t & 1023;
    float m = ord_decode(zenc[t]);
    m = (m >= 0.f) ? m : 0.2f * m;
    z[b * 1088 + o] = m;
}

// Small FC
__global__ void fc_kernel(const float* __restrict__ A, int lda,
                          const float* __restrict__ W,
                          const float* __restrict__ bias,
                          float* __restrict__ C, int ldc,
                          int Bn, int O, int Kd, int relu)
{
    int t = blockIdx.x * blockDim.x + threadIdx.x;
    if (t >= Bn * O) return;
    int b = t / O, o = t - b * O;
    const float* a = A + (long)b * lda;
    const float* w = W + (long)o * Kd;
    float s0 = 0.f, s1 = 0.f, s2 = 0.f, s3 = 0.f;
    int k = 0;
    for (; k + 3 < Kd; k += 4) {
        s0 = fmaf(a[k],     w[k],     s0);
        s1 = fmaf(a[k + 1], w[k + 1], s1);
        s2 = fmaf(a[k + 2], w[k + 2], s2);
        s3 = fmaf(a[k + 3], w[k + 3], s3);
    }
    for (; k < Kd; k++) s0 = fmaf(a[k], w[k], s0);
    float s = (s0 + s1) + (s2 + s3) + (bias ? bias[o] : 0.f);
    if (relu) s = (s >= 0.f) ? s : 0.2f * s;
    C[(long)b * ldc + o] = s;
}

// ---------------------------------------------------------------------------
static void run_layer(const float* feat, int lda, int d, int outc,
                      const float* W, float* catOut,
                      float* G, float* xx, int* idxp, float* Wuv, float* uv)
{
    xx_kernel<<<(BB * NN + 255) / 256, 256>>>(feat, lda, d, xx);

    dim3 gG(NN / BN, NN / BM, BB);
    gemm_nt<0><<<gG, 256>>>(feat, feat, G, nullptr, d, lda, lda, NN,
                            (long)NN * lda, (long)NN * lda, (long)NN * NN);

    topk_kernel<<<dim3(NN, BB), 256>>>(G, xx, idxp);

    int nw = 2 * outc * d;
    wuv_kernel<<<(nw + 255) / 256, 256>>>(W, Wuv, outc, d);

    dim3 gu((2 * outc) / BN, (BB * NN) / BM, 1);
    gemm_nt<0><<<gu, 256>>>(feat, Wuv, uv, nullptr, d, lda, d, 2 * outc, 0, 0, 0);

    gather_max_kernel<<<BB * NN, outc>>>(uv, idxp, catOut, outc);
}

extern "C" void kernel_launch(void* const* d_in, const int* in_sizes, int n_in,
                              void* d_out, int out_size)
{
    const float* x   = (const float*)d_in[0];
    const float* y   = (const float*)d_in[1];
    const float* W0  = (const float*)d_in[2];
    const float* W1  = (const float*)d_in[3];
    const float* W2  = (const float*)d_in[4];
    const float* W3  = (const float*)d_in[5];
    const float* W4  = (const float*)d_in[6];
    const float* L0  = (const float*)d_in[7];
    const float* L1  = (const float*)d_in[8];
    const float* L2w = (const float*)d_in[9];
    const float* L2b = (const float*)d_in[10];
    const float* F0w = (const float*)d_in[11];
    const float* F0b = (const float*)d_in[12];
    const float* F1w = (const float*)d_in[13];
    const float* F1b = (const float*)d_in[14];
    float* out = (float*)d_out;

    float *G, *cat, *uv, *xx, *Wuv, *z, *ye0, *z1, *z2;
    unsigned int* zenc;
    int* idxp;
    cudaGetSymbolAddress((void**)&G,    g_G);
    cudaGetSymbolAddress((void**)&cat,  g_cat);
    cudaGetSymbolAddress((void**)&uv,   g_uv);
    cudaGetSymbolAddress((void**)&xx,   g_xx);
    cudaGetSymbolAddress((void**)&Wuv,  g_Wuv);
    cudaGetSymbolAddress((void**)&z,    g_z);
    cudaGetSymbolAddress((void**)&ye0,  g_ye0);
    cudaGetSymbolAddress((void**)&z1,   g_z1);
    cudaGetSymbolAddress((void**)&z2,   g_z2);
    cudaGetSymbolAddress((void**)&zenc, g_zenc);
    cudaGetSymbolAddress((void**)&idxp, g_idx);

    run_layer(x,         6,   6,   64,  W0, cat + 0,   G, xx, idxp, Wuv, uv);
    run_layer(cat + 0,   512, 64,  64,  W1, cat + 64,  G, xx, idxp, Wuv, uv);
    run_layer(cat + 64,  512, 64,  128, W2, cat + 128, G, xx, idxp, Wuv, uv);
    run_layer(cat + 128, 512, 128, 256, W3, cat + 256, G, xx, idxp, Wuv, uv);

    // W4 GEMM fused with column max
    zenc_init_kernel<<<(BB * 1024 + 255) / 256, 256>>>(zenc);
    dim3 g4(1024 / BN, (BB * NN) / BM, 1);
    gemm_nt<1><<<g4, 256>>>(cat, W4, nullptr, zenc, 512, 512, 512, 0, 0, 0, 0);
    zenc_decode_kernel<<<(BB * 1024 + 255) / 256, 256>>>(zenc, z);

    fc_kernel<<<1, 256>>>(y, 16, F0w, F0b, ye0, 16, BB, 16, 16, 1);
    fc_kernel<<<(BB * 64 + 255) / 256, 256>>>(ye0, 16, F1w, F1b, z + 1024, 1088,
                                              BB, 64, 16, 1);

    fc_kernel<<<(BB * 512 + 255) / 256, 256>>>(z, 1088, L0, nullptr, z1, 512,
                                               BB, 512, 1088, 1);
    fc_kernel<<<(BB * 256 + 255) / 256, 256>>>(z1, 512, L1, nullptr, z2, 256,
                                               BB, 256, 512, 1);
    fc_kernel<<<1, 16>>>(z2, 256, L2w, L2b, out, 1, BB, 1, 256, 0);
}

// round 6
// speedup vs baseline: 1.6453x; 1.0156x over previous
#include <cuda_runtime.h>
#include <cuda_bf16.h>
#include <math.h>
#include <stdint.h>

// ---------------------------------------------------------------------------
// DGCNN discriminator, B=16, N=1024, K=20.
// Round 6: GEMMs via mma.sync m16n8k16 bf16 with 3-way bf16 split (6 terms):
//   a = ah + am + al (24 mantissa bits) ->
//   a*b ~= ah*bh + ah*bm + am*bh + ah*bl + al*bh + am*bm   (error ~2^-24)
// fp32 accumulators -> fp32-grade accuracy on the tensor pipe.
// Block tile 128x128, BK=32, 8 warps (2x4), warp tile 64x32.
// ---------------------------------------------------------------------------

#define BB 16
#define NN 1024
#define KNNK 20
#define CATC 512

__device__ float g_G[BB * NN * NN];
__device__ float g_cat[BB * NN * CATC];
__device__ float g_uv[BB * NN * 512];
__device__ float g_xx[BB * NN];
__device__ int   g_idx[BB * NN * KNNK];
__device__ float g_Wuv[512 * 256];
__device__ unsigned int g_zenc[BB * 1024];
__device__ float g_z[BB * 1088];
__device__ float g_ye0[BB * 16];
__device__ float g_z1[BB * 512];
__device__ float g_z2[BB * 256];

__device__ __forceinline__ unsigned int ord_float(float v) {
    unsigned int u = __float_as_uint(v);
    return (u & 0x80000000u) ? ~u : (u | 0x80000000u);
}
__device__ __forceinline__ float ord_decode(unsigned int e) {
    unsigned int u = (e & 0x80000000u) ? (e ^ 0x80000000u) : ~e;
    return __uint_as_float(u);
}

// ---------------- warp-MMA primitives (baseline PTX, sm_80+) ---------------
__device__ __forceinline__ void ldsm4(uint32_t* r, const void* p) {
    uint32_t addr = (uint32_t)__cvta_generic_to_shared(p);
    asm volatile("ldmatrix.sync.aligned.m8n8.x4.shared.b16 {%0,%1,%2,%3}, [%4];"
                 : "=r"(r[0]), "=r"(r[1]), "=r"(r[2]), "=r"(r[3]) : "r"(addr));
}
__device__ __forceinline__ void mma_bf16(float* c, const uint32_t* a,
                                         const uint32_t* b) {
    asm volatile(
        "mma.sync.aligned.m16n8k16.row.col.f32.bf16.bf16.f32 "
        "{%0,%1,%2,%3}, {%4,%5,%6,%7}, {%8,%9}, {%0,%1,%2,%3};"
        : "+f"(c[0]), "+f"(c[1]), "+f"(c[2]), "+f"(c[3])
        : "r"(a[0]), "r"(a[1]), "r"(a[2]), "r"(a[3]), "r"(b[0]), "r"(b[1]));
}
__device__ __forceinline__ uint32_t pack2(float x, float y) {
    __nv_bfloat162 v = __floats2bfloat162_rn(x, y);
    uint32_t r; memcpy(&r, &v, 4); return r;
}

#define LDSTR 40            // row stride in bf16 (80 B = 5*16B -> LDSM conflict-free)
#define TILE_BF (128 * LDSTR)
#define SMEM_MMA (6 * TILE_BF * 2)   // 61440 B

// 3-way bf16 split: a = h + m + l  (all residual subtractions exact in fp32)
__device__ __forceinline__ void split3(float a, float& h, float& m, float& l) {
    h = __bfloat162float(__float2bfloat16_rn(a));
    float r1 = a - h;
    m = __bfloat162float(__float2bfloat16_rn(r1));
    l = r1 - m;   // rounded to bf16 at pack time
}

// ---------------------------------------------------------------------------
// C[M,N] = A[M,Kd] @ W[N,Kd]^T, fp32 in/out, bf16 split-3 internal, fp32 acc.
// Grid (N/128, M/128, batches), 256 threads.
// EPI==0: store C.  EPI==1: atomicMax ord column max into zenc[(row0>>10)*1024+col].
// ---------------------------------------------------------------------------
template<int EPI>
__global__ __launch_bounds__(256, 1)
void mma_gemm(const float* __restrict__ A, const float* __restrict__ Wt,
              float* __restrict__ C, unsigned int* __restrict__ zenc,
              int Kd, int lda, int ldw, int ldc,
              long bA, long bW, long bC)
{
    extern __shared__ __nv_bfloat16 dsm[];
    __nv_bfloat16* Ah = dsm;
    __nv_bfloat16* Am = Ah + TILE_BF;
    __nv_bfloat16* Al = Am + TILE_BF;
    __nv_bfloat16* Bh = Al + TILE_BF;
    __nv_bfloat16* Bm = Bh + TILE_BF;
    __nv_bfloat16* Bl = Bm + TILE_BF;

    int bz = blockIdx.z;
    A  += (long)bz * bA;
    Wt += (long)bz * bW;
    C  += (long)bz * bC;

    int tid = threadIdx.x;
    int lane = tid & 31, wid = tid >> 5;
    int warpm = wid >> 2;          // 0..1 -> 64 rows each
    int warpn = wid & 3;           // 0..3 -> 32 cols each
    int row0 = blockIdx.y * 128, col0 = blockIdx.x * 128;

    int lr = tid >> 1;             // loader row 0..127
    int kh = (tid & 1) << 4;       // loader k half: 0 / 16
    const float* Ar = A  + (long)(row0 + lr) * lda;
    const float* Wr = Wt + (long)(col0 + lr) * ldw;
    const bool vec = ((lda & 3) == 0) && ((ldw & 3) == 0) && ((Kd & 31) == 0);

    float acc[4][4][4];
    #pragma unroll
    for (int i = 0; i < 4; i++)
        #pragma unroll
        for (int j = 0; j < 4; j++)
            #pragma unroll
            for (int q = 0; q < 4; q++) acc[i][j][q] = 0.f;

    for (int k0 = 0; k0 < Kd; k0 += 32) {
        // ---- stage tile: fp32 load, 3-way bf16 split ----
        float fa[16], fb[16];
        if (vec) {
            #pragma unroll
            for (int q = 0; q < 4; q++) {
                *(float4*)&fa[q * 4] = *(const float4*)(Ar + k0 + kh + q * 4);
                *(float4*)&fb[q * 4] = *(const float4*)(Wr + k0 + kh + q * 4);
            }
        } else {
            #pragma unroll
            for (int j = 0; j < 16; j++) {
                int gk = k0 + kh + j;
                fa[j] = (gk < Kd) ? Ar[gk] : 0.f;
                fb[j] = (gk < Kd) ? Wr[gk] : 0.f;
            }
        }
        #pragma unroll
        for (int j = 0; j < 8; j++) {
            int c = lr * LDSTR + kh + 2 * j;
            float h0, m0, l0, h1, m1, l1;
            split3(fa[2 * j], h0, m0, l0);
            split3(fa[2 * j + 1], h1, m1, l1);
            *(uint32_t*)&Ah[c] = pack2(h0, h1);
            *(uint32_t*)&Am[c] = pack2(m0, m1);
            *(uint32_t*)&Al[c] = pack2(l0, l1);
            split3(fb[2 * j], h0, m0, l0);
            split3(fb[2 * j + 1], h1, m1, l1);
            *(uint32_t*)&Bh[c] = pack2(h0, h1);
            *(uint32_t*)&Bm[c] = pack2(m0, m1);
            *(uint32_t*)&Bl[c] = pack2(l0, l1);
        }
        __syncthreads();

        // ---- compute: 2 k16 steps ----
        #pragma unroll
        for (int ks = 0; ks < 32; ks += 16) {
            int arow = warpm * 64 + (lane & 15);
            int acol = ks + ((lane >> 4) << 3);
            int brow = warpn * 32 + (lane & 15);

            uint32_t a_h[4][4], a_m[4][4], a_l[4][4];
            #pragma unroll
            for (int mi = 0; mi < 4; mi++) {
                int off = (arow + mi * 16) * LDSTR + acol;
                ldsm4(a_h[mi], &Ah[off]);
                ldsm4(a_m[mi], &Am[off]);
                ldsm4(a_l[mi], &Al[off]);
            }
            uint32_t b_h[4][2], b_m[4][2], b_l[4][2];
            #pragma unroll
            for (int nq = 0; nq < 2; nq++) {
                int off = (brow + nq * 16) * LDSTR + acol;
                uint32_t t[4];
                ldsm4(t, &Bh[off]);
                b_h[2 * nq][0] = t[0]; b_h[2 * nq][1] = t[2];
                b_h[2 * nq + 1][0] = t[1]; b_h[2 * nq + 1][1] = t[3];
                ldsm4(t, &Bm[off]);
                b_m[2 * nq][0] = t[0]; b_m[2 * nq][1] = t[2];
                b_m[2 * nq + 1][0] = t[1]; b_m[2 * nq + 1][1] = t[3];
                ldsm4(t, &Bl[off]);
                b_l[2 * nq][0] = t[0]; b_l[2 * nq][1] = t[2];
                b_l[2 * nq + 1][0] = t[1]; b_l[2 * nq + 1][1] = t[3];
            }
            #pragma unroll
            for (int mi = 0; mi < 4; mi++)
                #pragma unroll
                for (int nj = 0; nj < 4; nj++) {
                    mma_bf16(acc[mi][nj], a_h[mi], b_h[nj]);
                    mma_bf16(acc[mi][nj], a_h[mi], b_m[nj]);
                    mma_bf16(acc[mi][nj], a_m[mi], b_h[nj]);
                    mma_bf16(acc[mi][nj], a_h[mi], b_l[nj]);
                    mma_bf16(acc[mi][nj], a_l[mi], b_h[nj]);
                    mma_bf16(acc[mi][nj], a_m[mi], b_m[nj]);
                }
        }
        __syncthreads();
    }

    // ---- epilogue ----
    int g = lane >> 2, tg = lane & 3;
    if (EPI == 0) {
        #pragma unroll
        for (int mi = 0; mi < 4; mi++) {
            int r = row0 + warpm * 64 + mi * 16 + g;
            #pragma unroll
            for (int nj = 0; nj < 4; nj++) {
                int c = col0 + warpn * 32 + nj * 8 + tg * 2;
                *(float2*)&C[(long)r * ldc + c] =
                    make_float2(acc[mi][nj][0], acc[mi][nj][1]);
                *(float2*)&C[(long)(r + 8) * ldc + c] =
                    make_float2(acc[mi][nj][2], acc[mi][nj][3]);
            }
        }
    } else {
        int bidx = row0 >> 10;
        #pragma unroll
        for (int nj = 0; nj < 4; nj++) {
            #pragma unroll
            for (int h = 0; h < 2; h++) {
                float v = fmaxf(acc[0][nj][h], acc[0][nj][h + 2]);
                #pragma unroll
                for (int mi = 1; mi < 4; mi++)
                    v = fmaxf(v, fmaxf(acc[mi][nj][h], acc[mi][nj][h + 2]));
                v = fmaxf(v, __shfl_xor_sync(0xFFFFFFFFu, v, 4));
                v = fmaxf(v, __shfl_xor_sync(0xFFFFFFFFu, v, 8));
                v = fmaxf(v, __shfl_xor_sync(0xFFFFFFFFu, v, 16));
                if (lane < 4)
                    atomicMax(&zenc[bidx * 1024 + col0 + warpn * 32 + nj * 8 +
                                    lane * 2 + h],
                              ord_float(v));
            }
        }
    }
}

// ---------------------------------------------------------------------------
// xx[p] = sum_c feat[p, c]^2
__global__ void xx_kernel(const float* __restrict__ feat, int lda, int d,
                          float* __restrict__ xx)
{
    int p = blockIdx.x * blockDim.x + threadIdx.x;
    if (p >= BB * NN) return;
    const float* r = feat + (long)p * lda;
    float s = 0.f;
    for (int c = 0; c < d; c++) s = fmaf(r[c], r[c], s);
    xx[p] = s;
}

// Register-resident top-20 with exact jax tie-break.
__global__ __launch_bounds__(256)
void topk_kernel(const float* __restrict__ G, const float* __restrict__ xx,
                 int* __restrict__ idx)
{
    int b = blockIdx.y, i = blockIdx.x;
    const float* Grow = G + ((long)b * NN + i) * NN;
    const float* xxb  = xx + b * NN;
    int t = threadIdx.x;
    int lane = t & 31, warp = t >> 5;

    __shared__ unsigned long long wkey[8];

    float xi = xxb[i];
    int j0 = t * 4;
    float4 g4  = *(const float4*)&Grow[j0];
    float4 xx4 = *(const float4*)&xxb[j0];

    unsigned long long key[4];
    {
        float gg[4] = {g4.x, g4.y, g4.z, g4.w};
        float xj[4] = {xx4.x, xx4.y, xx4.z, xx4.w};
        #pragma unroll
        for (int q = 0; q < 4; q++) {
            float inner = -2.0f * gg[q];
            float v = -xi - inner - xj[q];
            key[q] = ((unsigned long long)ord_float(v) << 32)
                   | (unsigned int)(0xFFFFFFFFu - (unsigned int)(j0 + q));
        }
    }

    int* out = idx + ((long)b * NN + i) * KNNK;

    for (int kk = 0; kk < KNNK; kk++) {
        unsigned long long best = key[0];
        #pragma unroll
        for (int q = 1; q < 4; q++) best = max(best, key[q]);
        #pragma unroll
        for (int s = 16; s > 0; s >>= 1)
            best = max(best, __shfl_xor_sync(0xFFFFFFFFu, best, s));
        if (lane == 0) wkey[warp] = best;
        __syncthreads();
        unsigned long long win = wkey[0];
        #pragma unroll
        for (int w = 1; w < 8; w++) win = max(win, wkey[w]);
        int wj = (int)(0xFFFFFFFFu - (unsigned int)(win & 0xFFFFFFFFu));
        if (t == 0) out[kk] = wj;
        #pragma unroll
        for (int q = 0; q < 4; q++)
            if (key[q] == win) key[q] = 0ull;
        __syncthreads();
    }
}

// Wuv: rows [0,outc) = W[:,0:d];  rows [outc,2outc) = W[:,d:2d]-W[:,0:d]
__global__ void wuv_kernel(const float* __restrict__ W, float* __restrict__ Wuv,
                           int outc, int d)
{
    int t = blockIdx.x * blockDim.x + threadIdx.x;
    if (t >= 2 * outc * d) return;
    int r = t / d, c = t - r * d;
    if (r < outc) Wuv[t] = W[(long)r * 2 * d + c];
    else {
        int o = r - outc;
        Wuv[t] = W[(long)o * 2 * d + d + c] - W[(long)o * 2 * d + c];
    }
}

// out[p, o] = max_k lrelu(u[nbr, o] + v[p, o])
__global__ void gather_max_kernel(const float* __restrict__ uv,
                                  const int* __restrict__ idx,
                                  float* __restrict__ outp, int outc)
{
    int p = blockIdx.x;
    int b = p >> 10;
    int o = threadIdx.x;
    if (o >= outc) return;
    int ldu = 2 * outc;
    float vi = uv[(long)p * ldu + outc + o];
    const int* ip = idx + (long)p * KNNK;
    float m = -__builtin_huge_valf();
    #pragma unroll 4
    for (int kk = 0; kk < KNNK; kk++) {
        int j = ip[kk];
        float t = uv[((long)(b << 10) + j) * ldu + o] + vi;
        t = (t >= 0.f) ? t : 0.2f * t;
        m = fmaxf(m, t);
    }
    outp[(long)p * CATC + o] = m;
}

__global__ void zenc_init_kernel(unsigned int* __restrict__ zenc)
{
    int t = blockIdx.x * blockDim.x + threadIdx.x;
    if (t < BB * 1024) zenc[t] = 0u;
}

__global__ void zenc_decode_kernel(const unsigned int* __restrict__ zenc,
                                   float* __restrict__ z)
{
    int t = blockIdx.x * blockDim.x + threadIdx.x;
    if (t >= BB * 1024) return;
    int b = t >> 10, o = t & 1023;
    float m = ord_decode(zenc[t]);
    m = (m >= 0.f) ? m : 0.2f * m;
    z[b * 1088 + o] = m;
}

// Small FC
__global__ void fc_kernel(const float* __restrict__ A, int lda,
                          const float* __restrict__ W,
                          const float* __restrict__ bias,
                          float* __restrict__ C, int ldc,
                          int Bn, int O, int Kd, int relu)
{
    int t = blockIdx.x * blockDim.x + threadIdx.x;
    if (t >= Bn * O) return;
    int b = t / O, o = t - b * O;
    const float* a = A + (long)b * lda;
    const float* w = W + (long)o * Kd;
    float s0 = 0.f, s1 = 0.f, s2 = 0.f, s3 = 0.f;
    int k = 0;
    for (; k + 3 < Kd; k += 4) {
        s0 = fmaf(a[k],     w[k],     s0);
        s1 = fmaf(a[k + 1], w[k + 1], s1);
        s2 = fmaf(a[k + 2], w[k + 2], s2);
        s3 = fmaf(a[k + 3], w[k + 3], s3);
    }
    for (; k < Kd; k++) s0 = fmaf(a[k], w[k], s0);
    float s = (s0 + s1) + (s2 + s3) + (bias ? bias[o] : 0.f);
    if (relu) s = (s >= 0.f) ? s : 0.2f * s;
    C[(long)b * ldc + o] = s;
}

// ---------------------------------------------------------------------------
static void run_layer(const float* feat, int lda, int d, int outc,
                      const float* W, float* catOut,
                      float* G, float* xx, int* idxp, float* Wuv, float* uv)
{
    xx_kernel<<<(BB * NN + 255) / 256, 256>>>(feat, lda, d, xx);

    dim3 gG(NN / 128, NN / 128, BB);
    mma_gemm<0><<<gG, 256, SMEM_MMA>>>(feat, feat, G, nullptr, d, lda, lda, NN,
                                       (long)NN * lda, (long)NN * lda,
                                       (long)NN * NN);

    topk_kernel<<<dim3(NN, BB), 256>>>(G, xx, idxp);

    int nw = 2 * outc * d;
    wuv_kernel<<<(nw + 255) / 256, 256>>>(W, Wuv, outc, d);

    dim3 gu((2 * outc) / 128, (BB * NN) / 128, 1);
    mma_gemm<0><<<gu, 256, SMEM_MMA>>>(feat, Wuv, uv, nullptr, d, lda, d,
                                       2 * outc, 0, 0, 0);

    gather_max_kernel<<<BB * NN, outc>>>(uv, idxp, catOut, outc);
}

extern "C" void kernel_launch(void* const* d_in, const int* in_sizes, int n_in,
                              void* d_out, int out_size)
{
    const float* x   = (const float*)d_in[0];
    const float* y   = (const float*)d_in[1];
    const float* W0  = (const float*)d_in[2];
    const float* W1  = (const float*)d_in[3];
    const float* W2  = (const float*)d_in[4];
    const float* W3  = (const float*)d_in[5];
    const float* W4  = (const float*)d_in[6];
    const float* L0  = (const float*)d_in[7];
    const float* L1  = (const float*)d_in[8];
    const float* L2w = (const float*)d_in[9];
    const float* L2b = (const float*)d_in[10];
    const float* F0w = (const float*)d_in[11];
    const float* F0b = (const float*)d_in[12];
    const float* F1w = (const float*)d_in[13];
    const float* F1b = (const float*)d_in[14];
    float* out = (float*)d_out;

    cudaFuncSetAttribute(mma_gemm<0>,
                         cudaFuncAttributeMaxDynamicSharedMemorySize, SMEM_MMA);
    cudaFuncSetAttribute(mma_gemm<1>,
                         cudaFuncAttributeMaxDynamicSharedMemorySize, SMEM_MMA);

    float *G, *cat, *uv, *xx, *Wuv, *z, *ye0, *z1, *z2;
    unsigned int* zenc;
    int* idxp;
    cudaGetSymbolAddress((void**)&G,    g_G);
    cudaGetSymbolAddress((void**)&cat,  g_cat);
    cudaGetSymbolAddress((void**)&uv,   g_uv);
    cudaGetSymbolAddress((void**)&xx,   g_xx);
    cudaGetSymbolAddress((void**)&Wuv,  g_Wuv);
    cudaGetSymbolAddress((void**)&z,    g_z);
    cudaGetSymbolAddress((void**)&ye0,  g_ye0);
    cudaGetSymbolAddress((void**)&z1,   g_z1);
    cudaGetSymbolAddress((void**)&z2,   g_z2);
    cudaGetSymbolAddress((void**)&zenc, g_zenc);
    cudaGetSymbolAddress((void**)&idxp, g_idx);

    run_layer(x,         6,   6,   64,  W0, cat + 0,   G, xx, idxp, Wuv, uv);
    run_layer(cat + 0,   512, 64,  64,  W1, cat + 64,  G, xx, idxp, Wuv, uv);
    run_layer(cat + 64,  512, 64,  128, W2, cat + 128, G, xx, idxp, Wuv, uv);
    run_layer(cat + 128, 512, 128, 256, W3, cat + 256, G, xx, idxp, Wuv, uv);

    // W4 GEMM (tensor) fused with column max
    zenc_init_kernel<<<(BB * 1024 + 255) / 256, 256>>>(zenc);
    dim3 g4(1024 / 128, (BB * NN) / 128, 1);
    mma_gemm<1><<<g4, 256, SMEM_MMA>>>(cat, W4, nullptr, zenc, 512, 512, 512, 0,
                                       0, 0, 0);
    zenc_decode_kernel<<<(BB * 1024 + 255) / 256, 256>>>(zenc, z);

    fc_kernel<<<1, 256>>>(y, 16, F0w, F0b, ye0, 16, BB, 16, 16, 1);
    fc_kernel<<<(BB * 64 + 255) / 256, 256>>>(ye0, 16, F1w, F1b, z + 1024, 1088,
                                              BB, 64, 16, 1);

    fc_kernel<<<(BB * 512 + 255) / 256, 256>>>(z, 1088, L0, nullptr, z1, 512,
                                               BB, 512, 1088, 1);
    fc_kernel<<<(BB * 256 + 255) / 256, 256>>>(z1, 512, L1, nullptr, z2, 256,
                                               BB, 256, 512, 1);
    fc_kernel<<<1, 16>>>(z2, 256, L2w, L2b, out, 1, BB, 1, 256, 0);
}

// round 7
// speedup vs baseline: 1.7403x; 1.0577x over previous
#include <cuda_runtime.h>
#include <cuda_bf16.h>
#include <math.h>
#include <stdint.h>

// ---------------------------------------------------------------------------
// DGCNN discriminator, B=16, N=1024, K=20.
// Round 7: 6-term bf16 split expressed as K-extension (staged K' = 6*16 = 96
// per 16 original k), so the MMA mainloop is a plain m16n8k16 GEMM with
// standard register pressure (no spills, 2 blocks/SM).
// ---------------------------------------------------------------------------

#define BB 16
#define NN 1024
#define KNNK 20
#define CATC 512

__device__ float g_G[BB * NN * NN];
__device__ float g_cat[BB * NN * CATC];
__device__ float g_uv[BB * NN * 512];
__device__ float g_xx[BB * NN];
__device__ int   g_idx[BB * NN * KNNK];
__device__ float g_Wuv[512 * 256];
__device__ unsigned int g_zenc[BB * 1024];
__device__ float g_z[BB * 1088];
__device__ float g_ye0[BB * 16];
__device__ float g_z1[BB * 512];
__device__ float g_z2[BB * 256];

__device__ __forceinline__ unsigned int ord_float(float v) {
    unsigned int u = __float_as_uint(v);
    return (u & 0x80000000u) ? ~u : (u | 0x80000000u);
}
__device__ __forceinline__ float ord_decode(unsigned int e) {
    unsigned int u = (e & 0x80000000u) ? (e ^ 0x80000000u) : ~e;
    return __uint_as_float(u);
}

// ---------------- warp-MMA primitives (baseline PTX, sm_80+) ---------------
__device__ __forceinline__ void ldsm4(uint32_t* r, const void* p) {
    uint32_t addr = (uint32_t)__cvta_generic_to_shared(p);
    asm volatile("ldmatrix.sync.aligned.m8n8.x4.shared.b16 {%0,%1,%2,%3}, [%4];"
                 : "=r"(r[0]), "=r"(r[1]), "=r"(r[2]), "=r"(r[3]) : "r"(addr));
}
__device__ __forceinline__ void mma_bf16(float* c, const uint32_t* a,
                                         const uint32_t* b) {
    asm volatile(
        "mma.sync.aligned.m16n8k16.row.col.f32.bf16.bf16.f32 "
        "{%0,%1,%2,%3}, {%4,%5,%6,%7}, {%8,%9}, {%0,%1,%2,%3};"
        : "+f"(c[0]), "+f"(c[1]), "+f"(c[2]), "+f"(c[3])
        : "r"(a[0]), "r"(a[1]), "r"(a[2]), "r"(a[3]), "r"(b[0]), "r"(b[1]));
}
__device__ __forceinline__ uint32_t pack2(float x, float y) {
    __nv_bfloat162 v = __floats2bfloat162_rn(x, y);
    uint32_t r; memcpy(&r, &v, 4); return r;
}

// 3-way bf16 split: a ~= h + m + l (residual subtractions exact in fp32)
__device__ __forceinline__ void split3(float a, float& h, float& m, float& l) {
    h = __bfloat162float(__float2bfloat16_rn(a));
    float r1 = a - h;
    m = __bfloat162float(__float2bfloat16_rn(r1));
    l = r1 - m;
}

// Staged K' = 96 columns per 16 original k. Row stride 104 bf16 = 208 B
// (odd multiple of 16B -> ldmatrix conflict-free).
#define KP 96
#define LDS2 104
#define TILE2 (128 * LDS2)
#define SMEM_MMA (2 * TILE2 * 2)    // A + B staged tiles, bf16: 53248 B

// ---------------------------------------------------------------------------
// C[M,N] = A[M,Kd] @ W[N,Kd]^T, fp32 in/out, 6-term bf16 K-extension, fp32 acc.
// Grid (N/128, M/128, batches), 256 threads, 8 warps (2x4), warp tile 64x32.
// EPI==0: store C.  EPI==1: atomicMax ord column max into zenc[(row0>>10)*1024+col].
// ---------------------------------------------------------------------------
template<int EPI>
__global__ __launch_bounds__(256, 2)
void mma_gemm(const float* __restrict__ A, const float* __restrict__ Wt,
              float* __restrict__ C, unsigned int* __restrict__ zenc,
              int Kd, int lda, int ldw, int ldc,
              long bA, long bW, long bC)
{
    extern __shared__ __nv_bfloat16 dsm[];
    __nv_bfloat16* As = dsm;            // [128][LDS2]
    __nv_bfloat16* Bs = dsm + TILE2;    // [128][LDS2]

    int bz = blockIdx.z;
    A  += (long)bz * bA;
    Wt += (long)bz * bW;
    C  += (long)bz * bC;

    int tid = threadIdx.x;
    int lane = tid & 31, wid = tid >> 5;
    int warpm = wid >> 2;              // 0..1 -> 64 rows
    int warpn = wid & 3;               // 0..3 -> 32 cols
    int row0 = blockIdx.y * 128, col0 = blockIdx.x * 128;

    int lr = tid >> 1;                 // loader row 0..127
    int kh = (tid & 1) << 3;           // loader k-offset within 16: 0 / 8
    const float* Ar = A  + (long)(row0 + lr) * lda;
    const float* Wr = Wt + (long)(col0 + lr) * ldw;
    const bool vec = ((lda & 3) == 0) && ((ldw & 3) == 0) && ((Kd & 15) == 0);

    float acc[4][4][4];
    #pragma unroll
    for (int i = 0; i < 4; i++)
        #pragma unroll
        for (int j = 0; j < 4; j++)
            #pragma unroll
            for (int q = 0; q < 4; q++) acc[i][j][q] = 0.f;

    int ntiles = (Kd + 15) >> 4;
    float fa[8], fb[8];

    // prologue: load tile 0 inputs into registers
    {
        int k0 = 0;
        if (vec) {
            *(float4*)&fa[0] = *(const float4*)(Ar + k0 + kh);
            *(float4*)&fa[4] = *(const float4*)(Ar + k0 + kh + 4);
            *(float4*)&fb[0] = *(const float4*)(Wr + k0 + kh);
            *(float4*)&fb[4] = *(const float4*)(Wr + k0 + kh + 4);
        } else {
            #pragma unroll
            for (int q = 0; q < 8; q++) {
                int gk = k0 + kh + q;
                fa[q] = (gk < Kd) ? Ar[gk] : 0.f;
                fb[q] = (gk < Kd) ? Wr[gk] : 0.f;
            }
        }
    }

    for (int t = 0; t < ntiles; t++) {
        // ---- stage regs -> smem with 3-way split, 6 K-slots ----
        {
            float ah[8], am[8], al[8], bh[8], bm[8], bl[8];
            #pragma unroll
            for (int q = 0; q < 8; q++) {
                split3(fa[q], ah[q], am[q], al[q]);
                split3(fb[q], bh[q], bm[q], bl[q]);
            }
            int rb = lr * LDS2 + kh;
            #pragma unroll
            for (int j = 0; j < 4; j++) {
                int c = rb + 2 * j;
                uint32_t p;
                // A slots: {ah, ah, am, am, ah, al} at cols 0,16,32,48,64,80
                p = pack2(ah[2 * j], ah[2 * j + 1]);
                *(uint32_t*)&As[c +  0] = p;
                *(uint32_t*)&As[c + 16] = p;
                *(uint32_t*)&As[c + 64] = p;
                p = pack2(am[2 * j], am[2 * j + 1]);
                *(uint32_t*)&As[c + 32] = p;
                *(uint32_t*)&As[c + 48] = p;
                p = pack2(al[2 * j], al[2 * j + 1]);
                *(uint32_t*)&As[c + 80] = p;
                // B slots: {bh, bm, bh, bm, bl, bh}
                p = pack2(bh[2 * j], bh[2 * j + 1]);
                *(uint32_t*)&Bs[c +  0] = p;
                *(uint32_t*)&Bs[c + 32] = p;
                *(uint32_t*)&Bs[c + 80] = p;
                p = pack2(bm[2 * j], bm[2 * j + 1]);
                *(uint32_t*)&Bs[c + 16] = p;
                *(uint32_t*)&Bs[c + 48] = p;
                p = pack2(bl[2 * j], bl[2 * j + 1]);
                *(uint32_t*)&Bs[c + 64] = p;
            }
        }
        __syncthreads();

        // ---- prefetch next tile inputs ----
        if (t + 1 < ntiles) {
            int k0 = (t + 1) << 4;
            if (vec) {
                *(float4*)&fa[0] = *(const float4*)(Ar + k0 + kh);
                *(float4*)&fa[4] = *(const float4*)(Ar + k0 + kh + 4);
                *(float4*)&fb[0] = *(const float4*)(Wr + k0 + kh);
                *(float4*)&fb[4] = *(const float4*)(Wr + k0 + kh + 4);
            } else {
                #pragma unroll
                for (int q = 0; q < 8; q++) {
                    int gk = k0 + kh + q;
                    fa[q] = (gk < Kd) ? Ar[gk] : 0.f;
                    fb[q] = (gk < Kd) ? Wr[gk] : 0.f;
                }
            }
        }

        // ---- plain MMA mainloop over staged K' = 96 ----
        #pragma unroll
        for (int ks = 0; ks < KP; ks += 16) {
            int arow = warpm * 64 + (lane & 15);
            int acol = ks + ((lane >> 4) << 3);
            int brow = warpn * 32 + (lane & 15);

            uint32_t af[4][4];
            #pragma unroll
            for (int mi = 0; mi < 4; mi++)
                ldsm4(af[mi], &As[(arow + mi * 16) * LDS2 + acol]);

            uint32_t bf[4][2];
            #pragma unroll
            for (int nq = 0; nq < 2; nq++) {
                uint32_t tt[4];
                ldsm4(tt, &Bs[(brow + nq * 16) * LDS2 + acol]);
                bf[2 * nq][0] = tt[0]; bf[2 * nq][1] = tt[2];
                bf[2 * nq + 1][0] = tt[1]; bf[2 * nq + 1][1] = tt[3];
            }
            #pragma unroll
            for (int mi = 0; mi < 4; mi++)
                #pragma unroll
                for (int nj = 0; nj < 4; nj++)
                    mma_bf16(acc[mi][nj], af[mi], bf[nj]);
        }
        __syncthreads();
    }

    // ---- epilogue ----
    int g = lane >> 2, tg = lane & 3;
    if (EPI == 0) {
        #pragma unroll
        for (int mi = 0; mi < 4; mi++) {
            int r = row0 + warpm * 64 + mi * 16 + g;
            #pragma unroll
            for (int nj = 0; nj < 4; nj++) {
                int c = col0 + warpn * 32 + nj * 8 + tg * 2;
                *(float2*)&C[(long)r * ldc + c] =
                    make_float2(acc[mi][nj][0], acc[mi][nj][1]);
                *(float2*)&C[(long)(r + 8) * ldc + c] =
                    make_float2(acc[mi][nj][2], acc[mi][nj][3]);
            }
        }
    } else {
        int bidx = row0 >> 10;
        #pragma unroll
        for (int nj = 0; nj < 4; nj++) {
            #pragma unroll
            for (int h = 0; h < 2; h++) {
                float v = fmaxf(acc[0][nj][h], acc[0][nj][h + 2]);
                #pragma unroll
                for (int mi = 1; mi < 4; mi++)
                    v = fmaxf(v, fmaxf(acc[mi][nj][h], acc[mi][nj][h + 2]));
                v = fmaxf(v, __shfl_xor_sync(0xFFFFFFFFu, v, 4));
                v = fmaxf(v, __shfl_xor_sync(0xFFFFFFFFu, v, 8));
                v = fmaxf(v, __shfl_xor_sync(0xFFFFFFFFu, v, 16));
                if (lane < 4)
                    atomicMax(&zenc[bidx * 1024 + col0 + warpn * 32 + nj * 8 +
                                    lane * 2 + h],
                              ord_float(v));
            }
        }
    }
}

// ---------------------------------------------------------------------------
// xx[p] = sum_c feat[p, c]^2
__global__ void xx_kernel(const float* __restrict__ feat, int lda, int d,
                          float* __restrict__ xx)
{
    int p = blockIdx.x * blockDim.x + threadIdx.x;
    if (p >= BB * NN) return;
    const float* r = feat + (long)p * lda;
    float s = 0.f;
    for (int c = 0; c < d; c++) s = fmaf(r[c], r[c], s);
    xx[p] = s;
}

// Register-resident top-20 with exact jax tie-break.
__global__ __launch_bounds__(256)
void topk_kernel(const float* __restrict__ G, const float* __restrict__ xx,
                 int* __restrict__ idx)
{
    int b = blockIdx.y, i = blockIdx.x;
    const float* Grow = G + ((long)b * NN + i) * NN;
    const float* xxb  = xx + b * NN;
    int t = threadIdx.x;
    int lane = t & 31, warp = t >> 5;

    __shared__ unsigned long long wkey[8];

    float xi = xxb[i];
    int j0 = t * 4;
    float4 g4  = *(const float4*)&Grow[j0];
    float4 xx4 = *(const float4*)&xxb[j0];

    unsigned long long key[4];
    {
        float gg[4] = {g4.x, g4.y, g4.z, g4.w};
        float xj[4] = {xx4.x, xx4.y, xx4.z, xx4.w};
        #pragma unroll
        for (int q = 0; q < 4; q++) {
            float inner = -2.0f * gg[q];
            float v = -xi - inner - xj[q];
            key[q] = ((unsigned long long)ord_float(v) << 32)
                   | (unsigned int)(0xFFFFFFFFu - (unsigned int)(j0 + q));
        }
    }

    int* out = idx + ((long)b * NN + i) * KNNK;

    for (int kk = 0; kk < KNNK; kk++) {
        unsigned long long best = key[0];
        #pragma unroll
        for (int q = 1; q < 4; q++) best = max(best, key[q]);
        #pragma unroll
        for (int s = 16; s > 0; s >>= 1)
            best = max(best, __shfl_xor_sync(0xFFFFFFFFu, best, s));
        if (lane == 0) wkey[warp] = best;
        __syncthreads();
        unsigned long long win = wkey[0];
        #pragma unroll
        for (int w = 1; w < 8; w++) win = max(win, wkey[w]);
        int wj = (int)(0xFFFFFFFFu - (unsigned int)(win & 0xFFFFFFFFu));
        if (t == 0) out[kk] = wj;
        #pragma unroll
        for (int q = 0; q < 4; q++)
            if (key[q] == win) key[q] = 0ull;
        __syncthreads();
    }
}

// Wuv: rows [0,outc) = W[:,0:d];  rows [outc,2outc) = W[:,d:2d]-W[:,0:d]
__global__ void wuv_kernel(const float* __restrict__ W, float* __restrict__ Wuv,
                           int outc, int d)
{
    int t = blockIdx.x * blockDim.x + threadIdx.x;
    if (t >= 2 * outc * d) return;
    int r = t / d, c = t - r * d;
    if (r < outc) Wuv[t] = W[(long)r * 2 * d + c];
    else {
        int o = r - outc;
        Wuv[t] = W[(long)o * 2 * d + d + c] - W[(long)o * 2 * d + c];
    }
}

// out[p, o] = max_k lrelu(u[nbr, o] + v[p, o])
__global__ void gather_max_kernel(const float* __restrict__ uv,
                                  const int* __restrict__ idx,
                                  float* __restrict__ outp, int outc)
{
    int p = blockIdx.x;
    int b = p >> 10;
    int o = threadIdx.x;
    if (o >= outc) return;
    int ldu = 2 * outc;
    float vi = uv[(long)p * ldu + outc + o];
    const int* ip = idx + (long)p * KNNK;
    float m = -__builtin_huge_valf();
    #pragma unroll 4
    for (int kk = 0; kk < KNNK; kk++) {
        int j = ip[kk];
        float t = uv[((long)(b << 10) + j) * ldu + o] + vi;
        t = (t >= 0.f) ? t : 0.2f * t;
        m = fmaxf(m, t);
    }
    outp[(long)p * CATC + o] = m;
}

__global__ void zenc_init_kernel(unsigned int* __restrict__ zenc)
{
    int t = blockIdx.x * blockDim.x + threadIdx.x;
    if (t < BB * 1024) zenc[t] = 0u;
}

__global__ void zenc_decode_kernel(const unsigned int* __restrict__ zenc,
                                   float* __restrict__ z)
{
    int t = blockIdx.x * blockDim.x + threadIdx.x;
    if (t >= BB * 1024) return;
    int b = t >> 10, o = t & 1023;
    float m = ord_decode(zenc[t]);
    m = (m >= 0.f) ? m : 0.2f * m;
    z[b * 1088 + o] = m;
}

// Small FC
__global__ void fc_kernel(const float* __restrict__ A, int lda,
                          const float* __restrict__ W,
                          const float* __restrict__ bias,
                          float* __restrict__ C, int ldc,
                          int Bn, int O, int Kd, int relu)
{
    int t = blockIdx.x * blockDim.x + threadIdx.x;
    if (t >= Bn * O) return;
    int b = t / O, o = t - b * O;
    const float* a = A + (long)b * lda;
    const float* w = W + (long)o * Kd;
    float s0 = 0.f, s1 = 0.f, s2 = 0.f, s3 = 0.f;
    int k = 0;
    for (; k + 3 < Kd; k += 4) {
        s0 = fmaf(a[k],     w[k],     s0);
        s1 = fmaf(a[k + 1], w[k + 1], s1);
        s2 = fmaf(a[k + 2], w[k + 2], s2);
        s3 = fmaf(a[k + 3], w[k + 3], s3);
    }
    for (; k < Kd; k++) s0 = fmaf(a[k], w[k], s0);
    float s = (s0 + s1) + (s2 + s3) + (bias ? bias[o] : 0.f);
    if (relu) s = (s >= 0.f) ? s : 0.2f * s;
    C[(long)b * ldc + o] = s;
}

// ---------------------------------------------------------------------------
static void run_layer(const float* feat, int lda, int d, int outc,
                      const float* W, float* catOut,
                      float* G, float* xx, int* idxp, float* Wuv, float* uv)
{
    xx_kernel<<<(BB * NN + 255) / 256, 256>>>(feat, lda, d, xx);

    dim3 gG(NN / 128, NN / 128, BB);
    mma_gemm<0><<<gG, 256, SMEM_MMA>>>(feat, feat, G, nullptr, d, lda, lda, NN,
                                       (long)NN * lda, (long)NN * lda,
                                       (long)NN * NN);

    topk_kernel<<<dim3(NN, BB), 256>>>(G, xx, idxp);

    int nw = 2 * outc * d;
    wuv_kernel<<<(nw + 255) / 256, 256>>>(W, Wuv, outc, d);

    dim3 gu((2 * outc) / 128, (BB * NN) / 128, 1);
    mma_gemm<0><<<gu, 256, SMEM_MMA>>>(feat, Wuv, uv, nullptr, d, lda, d,
                                       2 * outc, 0, 0, 0);

    gather_max_kernel<<<BB * NN, outc>>>(uv, idxp, catOut, outc);
}

extern "C" void kernel_launch(void* const* d_in, const int* in_sizes, int n_in,
                              void* d_out, int out_size)
{
    const float* x   = (const float*)d_in[0];
    const float* y   = (const float*)d_in[1];
    const float* W0  = (const float*)d_in[2];
    const float* W1  = (const float*)d_in[3];
    const float* W2  = (const float*)d_in[4];
    const float* W3  = (const float*)d_in[5];
    const float* W4  = (const float*)d_in[6];
    const float* L0  = (const float*)d_in[7];
    const float* L1  = (const float*)d_in[8];
    const float* L2w = (const float*)d_in[9];
    const float* L2b = (const float*)d_in[10];
    const float* F0w = (const float*)d_in[11];
    const float* F0b = (const float*)d_in[12];
    const float* F1w = (const float*)d_in[13];
    const float* F1b = (const float*)d_in[14];
    float* out = (float*)d_out;

    cudaFuncSetAttribute(mma_gemm<0>,
                         cudaFuncAttributeMaxDynamicSharedMemorySize, SMEM_MMA);
    cudaFuncSetAttribute(mma_gemm<1>,
                         cudaFuncAttributeMaxDynamicSharedMemorySize, SMEM_MMA);

    float *G, *cat, *uv, *xx, *Wuv, *z, *ye0, *z1, *z2;
    unsigned int* zenc;
    int* idxp;
    cudaGetSymbolAddress((void**)&G,    g_G);
    cudaGetSymbolAddress((void**)&cat,  g_cat);
    cudaGetSymbolAddress((void**)&uv,   g_uv);
    cudaGetSymbolAddress((void**)&xx,   g_xx);
    cudaGetSymbolAddress((void**)&Wuv,  g_Wuv);
    cudaGetSymbolAddress((void**)&z,    g_z);
    cudaGetSymbolAddress((void**)&ye0,  g_ye0);
    cudaGetSymbolAddress((void**)&z1,   g_z1);
    cudaGetSymbolAddress((void**)&z2,   g_z2);
    cudaGetSymbolAddress((void**)&zenc, g_zenc);
    cudaGetSymbolAddress((void**)&idxp, g_idx);

    run_layer(x,         6,   6,   64,  W0, cat + 0,   G, xx, idxp, Wuv, uv);
    run_layer(cat + 0,   512, 64,  64,  W1, cat + 64,  G, xx, idxp, Wuv, uv);
    run_layer(cat + 64,  512, 64,  128, W2, cat + 128, G, xx, idxp, Wuv, uv);
    run_layer(cat + 128, 512, 128, 256, W3, cat + 256, G, xx, idxp, Wuv, uv);

    // W4 GEMM (tensor) fused with column max
    zenc_init_kernel<<<(BB * 1024 + 255) / 256, 256>>>(zenc);
    dim3 g4(1024 / 128, (BB * NN) / 128, 1);
    mma_gemm<1><<<g4, 256, SMEM_MMA>>>(cat, W4, nullptr, zenc, 512, 512, 512, 0,
                                       0, 0, 0);
    zenc_decode_kernel<<<(BB * 1024 + 255) / 256, 256>>>(zenc, z);

    fc_kernel<<<1, 256>>>(y, 16, F0w, F0b, ye0, 16, BB, 16, 16, 1);
    fc_kernel<<<(BB * 64 + 255) / 256, 256>>>(ye0, 16, F1w, F1b, z + 1024, 1088,
                                              BB, 64, 16, 1);

    fc_kernel<<<(BB * 512 + 255) / 256, 256>>>(z, 1088, L0, nullptr, z1, 512,
                                               BB, 512, 1088, 1);
    fc_kernel<<<(BB * 256 + 255) / 256, 256>>>(z1, 512, L1, nullptr, z2, 256,
                                               BB, 256, 512, 1);
    fc_kernel<<<1, 16>>>(z2, 256, L2w, L2b, out, 1, BB, 1, 256, 0);
}

// round 8
// speedup vs baseline: 1.9523x; 1.1218x over previous
#include <cuda_runtime.h>
#include <cuda_bf16.h>
#include <cuda_fp16.h>
#include <math.h>
#include <stdint.h>

// ---------------------------------------------------------------------------
// DGCNN discriminator, B=16, N=1024, K=20.
// Round 8: 2-way fp16 split (11+11 mantissa bits), 3 terms via K-extension
// (staged K' = 3*16 = 48 per 16 original k). Plain m16n8k16 f16 mainloop.
//   a*b ~= ah*bh + ah*bl + al*bh   (drops al*bl ~ 2^-24)
// ---------------------------------------------------------------------------

#define BB 16
#define NN 1024
#define KNNK 20
#define CATC 512

__device__ float g_G[BB * NN * NN];
__device__ float g_cat[BB * NN * CATC];
__device__ float g_uv[BB * NN * 512];
__device__ float g_xx[BB * NN];
__device__ int   g_idx[BB * NN * KNNK];
__device__ float g_Wuv[512 * 256];
__device__ unsigned int g_zenc[BB * 1024];
__device__ float g_z[BB * 1088];
__device__ float g_ye0[BB * 16];
__device__ float g_z1[BB * 512];
__device__ float g_z2[BB * 256];

__device__ __forceinline__ unsigned int ord_float(float v) {
    unsigned int u = __float_as_uint(v);
    return (u & 0x80000000u) ? ~u : (u | 0x80000000u);
}
__device__ __forceinline__ float ord_decode(unsigned int e) {
    unsigned int u = (e & 0x80000000u) ? (e ^ 0x80000000u) : ~e;
    return __uint_as_float(u);
}

// ---------------- warp-MMA primitives (baseline PTX, sm_80+) ---------------
__device__ __forceinline__ void ldsm4(uint32_t* r, const void* p) {
    uint32_t addr = (uint32_t)__cvta_generic_to_shared(p);
    asm volatile("ldmatrix.sync.aligned.m8n8.x4.shared.b16 {%0,%1,%2,%3}, [%4];"
                 : "=r"(r[0]), "=r"(r[1]), "=r"(r[2]), "=r"(r[3]) : "r"(addr));
}
__device__ __forceinline__ void mma_f16(float* c, const uint32_t* a,
                                        const uint32_t* b) {
    asm volatile(
        "mma.sync.aligned.m16n8k16.row.col.f32.f16.f16.f32 "
        "{%0,%1,%2,%3}, {%4,%5,%6,%7}, {%8,%9}, {%0,%1,%2,%3};"
        : "+f"(c[0]), "+f"(c[1]), "+f"(c[2]), "+f"(c[3])
        : "r"(a[0]), "r"(a[1]), "r"(a[2]), "r"(a[3]), "r"(b[0]), "r"(b[1]));
}
__device__ __forceinline__ uint32_t packh2(float x, float y) {
    __half2 v = __floats2half2_rn(x, y);
    uint32_t r; memcpy(&r, &v, 4); return r;
}

// 2-way fp16 split: a ~= h + l, h = fp16(a), l = fp16(a - h).
__device__ __forceinline__ void split2h(float a, float& h, float& l) {
    h = __half2float(__float2half_rn(a));
    l = a - h;                         // exact in fp32; rounded to fp16 at pack
}

// Staged K' = 48 columns per 16 original k. Row stride 56 halves = 112 B
// (odd multiple of 16B -> ldmatrix conflict-free).
#define KP 48
#define LDS2 56
#define TILE2 (128 * LDS2)
#define SMEM_MMA (2 * TILE2 * 2)    // A + B staged tiles, fp16: 28672 B

// ---------------------------------------------------------------------------
// C[M,N] = A[M,Kd] @ W[N,Kd]^T, fp32 in/out, 3-term fp16 K-extension, fp32 acc.
// Grid (N/128, M/128, batches), 256 threads, 8 warps (2x4), warp tile 64x32.
// EPI==0: store C.  EPI==1: atomicMax ord column max into zenc[(row0>>10)*1024+col].
// ---------------------------------------------------------------------------
template<int EPI>
__global__ __launch_bounds__(256, 2)
void mma_gemm(const float* __restrict__ A, const float* __restrict__ Wt,
              float* __restrict__ C, unsigned int* __restrict__ zenc,
              int Kd, int lda, int ldw, int ldc,
              long bA, long bW, long bC)
{
    extern __shared__ __half dsm[];
    __half* As = dsm;            // [128][LDS2]
    __half* Bs = dsm + TILE2;    // [128][LDS2]

    int bz = blockIdx.z;
    A  += (long)bz * bA;
    Wt += (long)bz * bW;
    C  += (long)bz * bC;

    int tid = threadIdx.x;
    int lane = tid & 31, wid = tid >> 5;
    int warpm = wid >> 2;              // 0..1 -> 64 rows
    int warpn = wid & 3;               // 0..3 -> 32 cols
    int row0 = blockIdx.y * 128, col0 = blockIdx.x * 128;

    int lr = tid >> 1;                 // loader row 0..127
    int kh = (tid & 1) << 3;           // loader k-offset within 16: 0 / 8
    const float* Ar = A  + (long)(row0 + lr) * lda;
    const float* Wr = Wt + (long)(col0 + lr) * ldw;
    const bool vec = ((lda & 3) == 0) && ((ldw & 3) == 0) && ((Kd & 15) == 0);

    float acc[4][4][4];
    #pragma unroll
    for (int i = 0; i < 4; i++)
        #pragma unroll
        for (int j = 0; j < 4; j++)
            #pragma unroll
            for (int q = 0; q < 4; q++) acc[i][j][q] = 0.f;

    int ntiles = (Kd + 15) >> 4;
    float fa[8], fb[8];

    // prologue: load tile 0 inputs
    {
        if (vec) {
            *(float4*)&fa[0] = *(const float4*)(Ar + kh);
            *(float4*)&fa[4] = *(const float4*)(Ar + kh + 4);
            *(float4*)&fb[0] = *(const float4*)(Wr + kh);
            *(float4*)&fb[4] = *(const float4*)(Wr + kh + 4);
        } else {
            #pragma unroll
            for (int q = 0; q < 8; q++) {
                int gk = kh + q;
                fa[q] = (gk < Kd) ? Ar[gk] : 0.f;
                fb[q] = (gk < Kd) ? Wr[gk] : 0.f;
            }
        }
    }

    for (int t = 0; t < ntiles; t++) {
        // ---- stage regs -> smem with fp16 split, 3 K-slots ----
        {
            float ah[8], al[8], bh[8], bl[8];
            #pragma unroll
            for (int q = 0; q < 8; q++) {
                split2h(fa[q], ah[q], al[q]);
                split2h(fb[q], bh[q], bl[q]);
            }
            int rb = lr * LDS2 + kh;
            #pragma unroll
            for (int j = 0; j < 4; j++) {
                int c = rb + 2 * j;
                uint32_t p;
                // A slots: {ah, ah, al} at cols 0, 16, 32
                p = packh2(ah[2 * j], ah[2 * j + 1]);
                *(uint32_t*)&As[c +  0] = p;
                *(uint32_t*)&As[c + 16] = p;
                p = packh2(al[2 * j], al[2 * j + 1]);
                *(uint32_t*)&As[c + 32] = p;
                // B slots: {bh, bl, bh} at cols 0, 16, 32
                p = packh2(bh[2 * j], bh[2 * j + 1]);
                *(uint32_t*)&Bs[c +  0] = p;
                *(uint32_t*)&Bs[c + 32] = p;
                p = packh2(bl[2 * j], bl[2 * j + 1]);
                *(uint32_t*)&Bs[c + 16] = p;
            }
        }
        __syncthreads();

        // ---- prefetch next tile inputs ----
        if (t + 1 < ntiles) {
            int k0 = (t + 1) << 4;
            if (vec) {
                *(float4*)&fa[0] = *(const float4*)(Ar + k0 + kh);
                *(float4*)&fa[4] = *(const float4*)(Ar + k0 + kh + 4);
                *(float4*)&fb[0] = *(const float4*)(Wr + k0 + kh);
                *(float4*)&fb[4] = *(const float4*)(Wr + k0 + kh + 4);
            } else {
                #pragma unroll
                for (int q = 0; q < 8; q++) {
                    int gk = k0 + kh + q;
                    fa[q] = (gk < Kd) ? Ar[gk] : 0.f;
                    fb[q] = (gk < Kd) ? Wr[gk] : 0.f;
                }
            }
        }

        // ---- plain MMA mainloop over staged K' = 48 ----
        #pragma unroll
        for (int ks = 0; ks < KP; ks += 16) {
            int arow = warpm * 64 + (lane & 15);
            int acol = ks + ((lane >> 4) << 3);
            int brow = warpn * 32 + (lane & 15);

            uint32_t af[4][4];
            #pragma unroll
            for (int mi = 0; mi < 4; mi++)
                ldsm4(af[mi], &As[(arow + mi * 16) * LDS2 + acol]);

            uint32_t bf[4][2];
            #pragma unroll
            for (int nq = 0; nq < 2; nq++) {
                uint32_t tt[4];
                ldsm4(tt, &Bs[(brow + nq * 16) * LDS2 + acol]);
                bf[2 * nq][0] = tt[0]; bf[2 * nq][1] = tt[2];
                bf[2 * nq + 1][0] = tt[1]; bf[2 * nq + 1][1] = tt[3];
            }
            #pragma unroll
            for (int mi = 0; mi < 4; mi++)
                #pragma unroll
                for (int nj = 0; nj < 4; nj++)
                    mma_f16(acc[mi][nj], af[mi], bf[nj]);
        }
        __syncthreads();
    }

    // ---- epilogue ----
    int g = lane >> 2, tg = lane & 3;
    if (EPI == 0) {
        #pragma unroll
        for (int mi = 0; mi < 4; mi++) {
            int r = row0 + warpm * 64 + mi * 16 + g;
            #pragma unroll
            for (int nj = 0; nj < 4; nj++) {
                int c = col0 + warpn * 32 + nj * 8 + tg * 2;
                *(float2*)&C[(long)r * ldc + c] =
                    make_float2(acc[mi][nj][0], acc[mi][nj][1]);
                *(float2*)&C[(long)(r + 8) * ldc + c] =
                    make_float2(acc[mi][nj][2], acc[mi][nj][3]);
            }
        }
    } else {
        int bidx = row0 >> 10;
        #pragma unroll
        for (int nj = 0; nj < 4; nj++) {
            #pragma unroll
            for (int h = 0; h < 2; h++) {
                float v = fmaxf(acc[0][nj][h], acc[0][nj][h + 2]);
                #pragma unroll
                for (int mi = 1; mi < 4; mi++)
                    v = fmaxf(v, fmaxf(acc[mi][nj][h], acc[mi][nj][h + 2]));
                v = fmaxf(v, __shfl_xor_sync(0xFFFFFFFFu, v, 4));
                v = fmaxf(v, __shfl_xor_sync(0xFFFFFFFFu, v, 8));
                v = fmaxf(v, __shfl_xor_sync(0xFFFFFFFFu, v, 16));
                if (lane < 4)
                    atomicMax(&zenc[bidx * 1024 + col0 + warpn * 32 + nj * 8 +
                                    lane * 2 + h],
                              ord_float(v));
            }
        }
    }
}

// ---------------------------------------------------------------------------
// xx[p] = sum_c feat[p, c]^2
__global__ void xx_kernel(const float* __restrict__ feat, int lda, int d,
                          float* __restrict__ xx)
{
    int p = blockIdx.x * blockDim.x + threadIdx.x;
    if (p >= BB * NN) return;
    const float* r = feat + (long)p * lda;
    float s = 0.f;
    for (int c = 0; c < d; c++) s = fmaf(r[c], r[c], s);
    xx[p] = s;
}

// Register-resident top-20 with exact jax tie-break.
__global__ __launch_bounds__(256)
void topk_kernel(const float* __restrict__ G, const float* __restrict__ xx,
                 int* __restrict__ idx)
{
    int b = blockIdx.y, i = blockIdx.x;
    const float* Grow = G + ((long)b * NN + i) * NN;
    const float* xxb  = xx + b * NN;
    int t = threadIdx.x;
    int lane = t & 31, warp = t >> 5;

    __shared__ unsigned long long wkey[8];

    float xi = xxb[i];
    int j0 = t * 4;
    float4 g4  = *(const float4*)&Grow[j0];
    float4 xx4 = *(const float4*)&xxb[j0];

    unsigned long long key[4];
    {
        float gg[4] = {g4.x, g4.y, g4.z, g4.w};
        float xj[4] = {xx4.x, xx4.y, xx4.z, xx4.w};
        #pragma unroll
        for (int q = 0; q < 4; q++) {
            float inner = -2.0f * gg[q];
            float v = -xi - inner - xj[q];
            key[q] = ((unsigned long long)ord_float(v) << 32)
                   | (unsigned int)(0xFFFFFFFFu - (unsigned int)(j0 + q));
        }
    }

    int* out = idx + ((long)b * NN + i) * KNNK;

    for (int kk = 0; kk < KNNK; kk++) {
        unsigned long long best = key[0];
        #pragma unroll
        for (int q = 1; q < 4; q++) best = max(best, key[q]);
        #pragma unroll
        for (int s = 16; s > 0; s >>= 1)
            best = max(best, __shfl_xor_sync(0xFFFFFFFFu, best, s));
        if (lane == 0) wkey[warp] = best;
        __syncthreads();
        unsigned long long win = wkey[0];
        #pragma unroll
        for (int w = 1; w < 8; w++) win = max(win, wkey[w]);
        int wj = (int)(0xFFFFFFFFu - (unsigned int)(win & 0xFFFFFFFFu));
        if (t == 0) out[kk] = wj;
        #pragma unroll
        for (int q = 0; q < 4; q++)
            if (key[q] == win) key[q] = 0ull;
        __syncthreads();
    }
}

// Wuv: rows [0,outc) = W[:,0:d];  rows [outc,2outc) = W[:,d:2d]-W[:,0:d]
__global__ void wuv_kernel(const float* __restrict__ W, float* __restrict__ Wuv,
                           int outc, int d)
{
    int t = blockIdx.x * blockDim.x + threadIdx.x;
    if (t >= 2 * outc * d) return;
    int r = t / d, c = t - r * d;
    if (r < outc) Wuv[t] = W[(long)r * 2 * d + c];
    else {
        int o = r - outc;
        Wuv[t] = W[(long)o * 2 * d + d + c] - W[(long)o * 2 * d + c];
    }
}

// out[p, o] = max_k lrelu(u[nbr, o] + v[p, o])
__global__ void gather_max_kernel(const float* __restrict__ uv,
                                  const int* __restrict__ idx,
                                  float* __restrict__ outp, int outc)
{
    int p = blockIdx.x;
    int b = p >> 10;
    int o = threadIdx.x;
    if (o >= outc) return;
    int ldu = 2 * outc;
    float vi = uv[(long)p * ldu + outc + o];
    const int* ip = idx + (long)p * KNNK;
    float m = -__builtin_huge_valf();
    #pragma unroll 4
    for (int kk = 0; kk < KNNK; kk++) {
        int j = ip[kk];
        float t = uv[((long)(b << 10) + j) * ldu + o] + vi;
        t = (t >= 0.f) ? t : 0.2f * t;
        m = fmaxf(m, t);
    }
    outp[(long)p * CATC + o] = m;
}

__global__ void zenc_init_kernel(unsigned int* __restrict__ zenc)
{
    int t = blockIdx.x * blockDim.x + threadIdx.x;
    if (t < BB * 1024) zenc[t] = 0u;
}

__global__ void zenc_decode_kernel(const unsigned int* __restrict__ zenc,
                                   float* __restrict__ z)
{
    int t = blockIdx.x * blockDim.x + threadIdx.x;
    if (t >= BB * 1024) return;
    int b = t >> 10, o = t & 1023;
    float m = ord_decode(zenc[t]);
    m = (m >= 0.f) ? m : 0.2f * m;
    z[b * 1088 + o] = m;
}

// Small FC
__global__ void fc_kernel(const float* __restrict__ A, int lda,
                          const float* __restrict__ W,
                          const float* __restrict__ bias,
                          float* __restrict__ C, int ldc,
                          int Bn, int O, int Kd, int relu)
{
    int t = blockIdx.x * blockDim.x + threadIdx.x;
    if (t >= Bn * O) return;
    int b = t / O, o = t - b * O;
    const float* a = A + (long)b * lda;
    const float* w = W + (long)o * Kd;
    float s0 = 0.f, s1 = 0.f, s2 = 0.f, s3 = 0.f;
    int k = 0;
    for (; k + 3 < Kd; k += 4) {
        s0 = fmaf(a[k],     w[k],     s0);
        s1 = fmaf(a[k + 1], w[k + 1], s1);
        s2 = fmaf(a[k + 2], w[k + 2], s2);
        s3 = fmaf(a[k + 3], w[k + 3], s3);
    }
    for (; k < Kd; k++) s0 = fmaf(a[k], w[k], s0);
    float s = (s0 + s1) + (s2 + s3) + (bias ? bias[o] : 0.f);
    if (relu) s = (s >= 0.f) ? s : 0.2f * s;
    C[(long)b * ldc + o] = s;
}

// ---------------------------------------------------------------------------
static void run_layer(const float* feat, int lda, int d, int outc,
                      const float* W, float* catOut,
                      float* G, float* xx, int* idxp, float* Wuv, float* uv)
{
    xx_kernel<<<(BB * NN + 255) / 256, 256>>>(feat, lda, d, xx);

    dim3 gG(NN / 128, NN / 128, BB);
    mma_gemm<0><<<gG, 256, SMEM_MMA>>>(feat, feat, G, nullptr, d, lda, lda, NN,
                                       (long)NN * lda, (long)NN * lda,
                                       (long)NN * NN);

    topk_kernel<<<dim3(NN, BB), 256>>>(G, xx, idxp);

    int nw = 2 * outc * d;
    wuv_kernel<<<(nw + 255) / 256, 256>>>(W, Wuv, outc, d);

    dim3 gu((2 * outc) / 128, (BB * NN) / 128, 1);
    mma_gemm<0><<<gu, 256, SMEM_MMA>>>(feat, Wuv, uv, nullptr, d, lda, d,
                                       2 * outc, 0, 0, 0);

    gather_max_kernel<<<BB * NN, outc>>>(uv, idxp, catOut, outc);
}

extern "C" void kernel_launch(void* const* d_in, const int* in_sizes, int n_in,
                              void* d_out, int out_size)
{
    const float* x   = (const float*)d_in[0];
    const float* y   = (const float*)d_in[1];
    const float* W0  = (const float*)d_in[2];
    const float* W1  = (const float*)d_in[3];
    const float* W2  = (const float*)d_in[4];
    const float* W3  = (const float*)d_in[5];
    const float* W4  = (const float*)d_in[6];
    const float* L0  = (const float*)d_in[7];
    const float* L1  = (const float*)d_in[8];
    const float* L2w = (const float*)d_in[9];
    const float* L2b = (const float*)d_in[10];
    const float* F0w = (const float*)d_in[11];
    const float* F0b = (const float*)d_in[12];
    const float* F1w = (const float*)d_in[13];
    const float* F1b = (const float*)d_in[14];
    float* out = (float*)d_out;

    cudaFuncSetAttribute(mma_gemm<0>,
                         cudaFuncAttributeMaxDynamicSharedMemorySize, SMEM_MMA);
    cudaFuncSetAttribute(mma_gemm<1>,
                         cudaFuncAttributeMaxDynamicSharedMemorySize, SMEM_MMA);

    float *G, *cat, *uv, *xx, *Wuv, *z, *ye0, *z1, *z2;
    unsigned int* zenc;
    int* idxp;
    cudaGetSymbolAddress((void**)&G,    g_G);
    cudaGetSymbolAddress((void**)&cat,  g_cat);
    cudaGetSymbolAddress((void**)&uv,   g_uv);
    cudaGetSymbolAddress((void**)&xx,   g_xx);
    cudaGetSymbolAddress((void**)&Wuv,  g_Wuv);
    cudaGetSymbolAddress((void**)&z,    g_z);
    cudaGetSymbolAddress((void**)&ye0,  g_ye0);
    cudaGetSymbolAddress((void**)&z1,   g_z1);
    cudaGetSymbolAddress((void**)&z2,   g_z2);
    cudaGetSymbolAddress((void**)&zenc, g_zenc);
    cudaGetSymbolAddress((void**)&idxp, g_idx);

    run_layer(x,         6,   6,   64,  W0, cat + 0,   G, xx, idxp, Wuv, uv);
    run_layer(cat + 0,   512, 64,  64,  W1, cat + 64,  G, xx, idxp, Wuv, uv);
    run_layer(cat + 64,  512, 64,  128, W2, cat + 128, G, xx, idxp, Wuv, uv);
    run_layer(cat + 128, 512, 128, 256, W3, cat + 256, G, xx, idxp, Wuv, uv);

    // W4 GEMM (tensor) fused with column max
    zenc_init_kernel<<<(BB * 1024 + 255) / 256, 256>>>(zenc);
    dim3 g4(1024 / 128, (BB * NN) / 128, 1);
    mma_gemm<1><<<g4, 256, SMEM_MMA>>>(cat, W4, nullptr, zenc, 512, 512, 512, 0,
                                       0, 0, 0);
    zenc_decode_kernel<<<(BB * 1024 + 255) / 256, 256>>>(zenc, z);

    fc_kernel<<<1, 256>>>(y, 16, F0w, F0b, ye0, 16, BB, 16, 16, 1);
    fc_kernel<<<(BB * 64 + 255) / 256, 256>>>(ye0, 16, F1w, F1b, z + 1024, 1088,
                                              BB, 64, 16, 1);

    fc_kernel<<<(BB * 512 + 255) / 256, 256>>>(z, 1088, L0, nullptr, z1, 512,
                                               BB, 512, 1088, 1);
    fc_kernel<<<(BB * 256 + 255) / 256, 256>>>(z1, 512, L1, nullptr, z2, 256,
                                               BB, 256, 512, 1);
    fc_kernel<<<1, 16>>>(z2, 256, L2w, L2b, out, 1, BB, 1, 256, 0);
}

// round 9
// speedup vs baseline: 3.8177x; 1.9555x over previous
#include <cuda_runtime.h>
#include <cuda_bf16.h>
#include <cuda_fp16.h>
#include <math.h>
#include <stdint.h>

// ---------------------------------------------------------------------------
// DGCNN discriminator, B=16, N=1024, K=20.
// Round 9: warp-per-row register top-20 (no syncthreads, no smem tree),
// GEMMs via 3-term fp16-split m16n8k16 K-extension (unchanged from R8).
// ---------------------------------------------------------------------------

#define BB 16
#define NN 1024
#define KNNK 20
#define CATC 512

__device__ float g_G[BB * NN * NN];
__device__ float g_cat[BB * NN * CATC];
__device__ float g_uv[BB * NN * 512];
__device__ float g_xx[BB * NN];
__device__ int   g_idx[BB * NN * KNNK];
__device__ float g_Wuv[512 * 256];
__device__ unsigned int g_zenc[BB * 1024];
__device__ float g_z[BB * 1088];
__device__ float g_ye0[BB * 16];
__device__ float g_z1[BB * 512];
__device__ float g_z2[BB * 256];

__device__ __forceinline__ unsigned int ord_float(float v) {
    unsigned int u = __float_as_uint(v);
    return (u & 0x80000000u) ? ~u : (u | 0x80000000u);
}
__device__ __forceinline__ float ord_decode(unsigned int e) {
    unsigned int u = (e & 0x80000000u) ? (e ^ 0x80000000u) : ~e;
    return __uint_as_float(u);
}

// ---------------- warp-MMA primitives (baseline PTX, sm_80+) ---------------
__device__ __forceinline__ void ldsm4(uint32_t* r, const void* p) {
    uint32_t addr = (uint32_t)__cvta_generic_to_shared(p);
    asm volatile("ldmatrix.sync.aligned.m8n8.x4.shared.b16 {%0,%1,%2,%3}, [%4];"
                 : "=r"(r[0]), "=r"(r[1]), "=r"(r[2]), "=r"(r[3]) : "r"(addr));
}
__device__ __forceinline__ void mma_f16(float* c, const uint32_t* a,
                                        const uint32_t* b) {
    asm volatile(
        "mma.sync.aligned.m16n8k16.row.col.f32.f16.f16.f32 "
        "{%0,%1,%2,%3}, {%4,%5,%6,%7}, {%8,%9}, {%0,%1,%2,%3};"
        : "+f"(c[0]), "+f"(c[1]), "+f"(c[2]), "+f"(c[3])
        : "r"(a[0]), "r"(a[1]), "r"(a[2]), "r"(a[3]), "r"(b[0]), "r"(b[1]));
}
__device__ __forceinline__ uint32_t packh2(float x, float y) {
    __half2 v = __floats2half2_rn(x, y);
    uint32_t r; memcpy(&r, &v, 4); return r;
}

// 2-way fp16 split: a ~= h + l, h = fp16(a), l = fp16(a - h).
__device__ __forceinline__ void split2h(float a, float& h, float& l) {
    h = __half2float(__float2half_rn(a));
    l = a - h;
}

// Staged K' = 48 columns per 16 original k. Row stride 56 halves = 112 B.
#define KP 48
#define LDS2 56
#define TILE2 (128 * LDS2)
#define SMEM_MMA (2 * TILE2 * 2)    // 28672 B

// ---------------------------------------------------------------------------
// C[M,N] = A[M,Kd] @ W[N,Kd]^T, fp32 in/out, 3-term fp16 K-extension, fp32 acc.
// ---------------------------------------------------------------------------
template<int EPI>
__global__ __launch_bounds__(256, 2)
void mma_gemm(const float* __restrict__ A, const float* __restrict__ Wt,
              float* __restrict__ C, unsigned int* __restrict__ zenc,
              int Kd, int lda, int ldw, int ldc,
              long bA, long bW, long bC)
{
    extern __shared__ __half dsm[];
    __half* As = dsm;            // [128][LDS2]
    __half* Bs = dsm + TILE2;    // [128][LDS2]

    int bz = blockIdx.z;
    A  += (long)bz * bA;
    Wt += (long)bz * bW;
    C  += (long)bz * bC;

    int tid = threadIdx.x;
    int lane = tid & 31, wid = tid >> 5;
    int warpm = wid >> 2;              // 0..1 -> 64 rows
    int warpn = wid & 3;               // 0..3 -> 32 cols
    int row0 = blockIdx.y * 128, col0 = blockIdx.x * 128;

    int lr = tid >> 1;                 // loader row 0..127
    int kh = (tid & 1) << 3;           // loader k-offset within 16: 0 / 8
    const float* Ar = A  + (long)(row0 + lr) * lda;
    const float* Wr = Wt + (long)(col0 + lr) * ldw;
    const bool vec = ((lda & 3) == 0) && ((ldw & 3) == 0) && ((Kd & 15) == 0);

    float acc[4][4][4];
    #pragma unroll
    for (int i = 0; i < 4; i++)
        #pragma unroll
        for (int j = 0; j < 4; j++)
            #pragma unroll
            for (int q = 0; q < 4; q++) acc[i][j][q] = 0.f;

    int ntiles = (Kd + 15) >> 4;
    float fa[8], fb[8];

    // prologue: load tile 0 inputs
    {
        if (vec) {
            *(float4*)&fa[0] = *(const float4*)(Ar + kh);
            *(float4*)&fa[4] = *(const float4*)(Ar + kh + 4);
            *(float4*)&fb[0] = *(const float4*)(Wr + kh);
            *(float4*)&fb[4] = *(const float4*)(Wr + kh + 4);
        } else {
            #pragma unroll
            for (int q = 0; q < 8; q++) {
                int gk = kh + q;
                fa[q] = (gk < Kd) ? Ar[gk] : 0.f;
                fb[q] = (gk < Kd) ? Wr[gk] : 0.f;
            }
        }
    }

    for (int t = 0; t < ntiles; t++) {
        // ---- stage regs -> smem with fp16 split, 3 K-slots ----
        {
            float ah[8], al[8], bh[8], bl[8];
            #pragma unroll
            for (int q = 0; q < 8; q++) {
                split2h(fa[q], ah[q], al[q]);
                split2h(fb[q], bh[q], bl[q]);
            }
            int rb = lr * LDS2 + kh;
            #pragma unroll
            for (int j = 0; j < 4; j++) {
                int c = rb + 2 * j;
                uint32_t p;
                // A slots: {ah, ah, al} at cols 0, 16, 32
                p = packh2(ah[2 * j], ah[2 * j + 1]);
                *(uint32_t*)&As[c +  0] = p;
                *(uint32_t*)&As[c + 16] = p;
                p = packh2(al[2 * j], al[2 * j + 1]);
                *(uint32_t*)&As[c + 32] = p;
                // B slots: {bh, bl, bh} at cols 0, 16, 32
                p = packh2(bh[2 * j], bh[2 * j + 1]);
                *(uint32_t*)&Bs[c +  0] = p;
                *(uint32_t*)&Bs[c + 32] = p;
                p = packh2(bl[2 * j], bl[2 * j + 1]);
                *(uint32_t*)&Bs[c + 16] = p;
            }
        }
        __syncthreads();

        // ---- prefetch next tile inputs ----
        if (t + 1 < ntiles) {
            int k0 = (t + 1) << 4;
            if (vec) {
                *(float4*)&fa[0] = *(const float4*)(Ar + k0 + kh);
                *(float4*)&fa[4] = *(const float4*)(Ar + k0 + kh + 4);
                *(float4*)&fb[0] = *(const float4*)(Wr + k0 + kh);
                *(float4*)&fb[4] = *(const float4*)(Wr + k0 + kh + 4);
            } else {
                #pragma unroll
                for (int q = 0; q < 8; q++) {
                    int gk = k0 + kh + q;
                    fa[q] = (gk < Kd) ? Ar[gk] : 0.f;
                    fb[q] = (gk < Kd) ? Wr[gk] : 0.f;
                }
            }
        }

        // ---- plain MMA mainloop over staged K' = 48 ----
        #pragma unroll
        for (int ks = 0; ks < KP; ks += 16) {
            int arow = warpm * 64 + (lane & 15);
            int acol = ks + ((lane >> 4) << 3);
            int brow = warpn * 32 + (lane & 15);

            uint32_t af[4][4];
            #pragma unroll
            for (int mi = 0; mi < 4; mi++)
                ldsm4(af[mi], &As[(arow + mi * 16) * LDS2 + acol]);

            uint32_t bf[4][2];
            #pragma unroll
            for (int nq = 0; nq < 2; nq++) {
                uint32_t tt[4];
                ldsm4(tt, &Bs[(brow + nq * 16) * LDS2 + acol]);
                bf[2 * nq][0] = tt[0]; bf[2 * nq][1] = tt[2];
                bf[2 * nq + 1][0] = tt[1]; bf[2 * nq + 1][1] = tt[3];
            }
            #pragma unroll
            for (int mi = 0; mi < 4; mi++)
                #pragma unroll
                for (int nj = 0; nj < 4; nj++)
                    mma_f16(acc[mi][nj], af[mi], bf[nj]);
        }
        __syncthreads();
    }

    // ---- epilogue ----
    int g = lane >> 2, tg = lane & 3;
    if (EPI == 0) {
        #pragma unroll
        for (int mi = 0; mi < 4; mi++) {
            int r = row0 + warpm * 64 + mi * 16 + g;
            #pragma unroll
            for (int nj = 0; nj < 4; nj++) {
                int c = col0 + warpn * 32 + nj * 8 + tg * 2;
                *(float2*)&C[(long)r * ldc + c] =
                    make_float2(acc[mi][nj][0], acc[mi][nj][1]);
                *(float2*)&C[(long)(r + 8) * ldc + c] =
                    make_float2(acc[mi][nj][2], acc[mi][nj][3]);
            }
        }
    } else {
        int bidx = row0 >> 10;
        #pragma unroll
        for (int nj = 0; nj < 4; nj++) {
            #pragma unroll
            for (int h = 0; h < 2; h++) {
                float v = fmaxf(acc[0][nj][h], acc[0][nj][h + 2]);
                #pragma unroll
                for (int mi = 1; mi < 4; mi++)
                    v = fmaxf(v, fmaxf(acc[mi][nj][h], acc[mi][nj][h + 2]));
                v = fmaxf(v, __shfl_xor_sync(0xFFFFFFFFu, v, 4));
                v = fmaxf(v, __shfl_xor_sync(0xFFFFFFFFu, v, 8));
                v = fmaxf(v, __shfl_xor_sync(0xFFFFFFFFu, v, 16));
                if (lane < 4)
                    atomicMax(&zenc[bidx * 1024 + col0 + warpn * 32 + nj * 8 +
                                    lane * 2 + h],
                              ord_float(v));
            }
        }
    }
}

// ---------------------------------------------------------------------------
// xx[p] = sum_c feat[p, c]^2
__global__ void xx_kernel(const float* __restrict__ feat, int lda, int d,
                          float* __restrict__ xx)
{
    int p = blockIdx.x * blockDim.x + threadIdx.x;
    if (p >= BB * NN) return;
    const float* r = feat + (long)p * lda;
    float s = 0.f;
    for (int c = 0; c < d; c++) s = fmaf(r[c], r[c], s);
    xx[p] = s;
}

// ---------------------------------------------------------------------------
// Warp-per-row top-20.  Each warp: 32 dist values/thread in registers
// (j = q*32 + lane), per-thread running (max, 2nd-max), 5-shfl u64 butterfly
// per iteration.  No __syncthreads, no smem.  Exact jax tie-break via packed
// (ord-float << 32) | (0xFFFFFFFF - j).
// ---------------------------------------------------------------------------
__global__ __launch_bounds__(256)
void topk_kernel(const float* __restrict__ G, const float* __restrict__ xx,
                 int* __restrict__ idx)
{
    int warp = threadIdx.x >> 5, lane = threadIdx.x & 31;
    int row = blockIdx.x * 8 + warp;          // 0 .. BB*NN-1
    int b = row >> 10, i = row & 1023;
    const float* Grow = G + (long)row * NN;   // row = b*NN + i
    const float* xxb  = xx + (b << 10);
    float xi = xxb[i];

    float v[32];
    #pragma unroll
    for (int q = 0; q < 32; q++) {
        int j = q * 32 + lane;
        float inner = -2.0f * Grow[j];
        v[q] = -xi - inner - xxb[j];
    }

    // per-thread top-2 (strict > keeps lowest q on ties = lowest j)
    float m1v = v[0], m2v = -__builtin_huge_valf();
    int m1q = 0, m2q = -1;
    #pragma unroll
    for (int q = 1; q < 32; q++) {
        if (v[q] > m1v) { m2v = m1v; m2q = m1q; m1v = v[q]; m1q = q; }
        else if (v[q] > m2v) { m2v = v[q]; m2q = q; }
    }

    int* out = idx + (long)row * KNNK;
    for (int kk = 0; kk < KNNK; kk++) {
        unsigned long long key =
            ((unsigned long long)ord_float(m1v) << 32)
            | (unsigned int)(0xFFFFFFFFu - (unsigned int)(m1q * 32 + lane));
        unsigned long long best = key;
        #pragma unroll
        for (int s = 16; s > 0; s >>= 1) {
            unsigned long long o = __shfl_xor_sync(0xFFFFFFFFu, best, s);
            if (o > best) best = o;
        }
        if (lane == 0)
            out[kk] = (int)(0xFFFFFFFFu - (unsigned int)(best & 0xFFFFFFFFu));

        if (key == best) {          // exactly one thread (j unique in key)
            #pragma unroll
            for (int q = 0; q < 32; q++)     // predicated clear, regs stay regs
                if (q == m1q) v[q] = -__builtin_huge_valf();
            if (m2q >= 0) {
                m1v = m2v; m1q = m2q; m2q = -1;
            } else {
                m1v = v[0]; m1q = 0;
                m2v = -__builtin_huge_valf(); m2q = -1;
                #pragma unroll
                for (int q = 1; q < 32; q++) {
                    if (v[q] > m1v) { m2v = m1v; m2q = m1q; m1v = v[q]; m1q = q; }
                    else if (v[q] > m2v) { m2v = v[q]; m2q = q; }
                }
            }
        }
    }
}

// Wuv: rows [0,outc) = W[:,0:d];  rows [outc,2outc) = W[:,d:2d]-W[:,0:d]
__global__ void wuv_kernel(const float* __restrict__ W, float* __restrict__ Wuv,
                           int outc, int d)
{
    int t = blockIdx.x * blockDim.x + threadIdx.x;
    if (t >= 2 * outc * d) return;
    int r = t / d, c = t - r * d;
    if (r < outc) Wuv[t] = W[(long)r * 2 * d + c];
    else {
        int o = r - outc;
        Wuv[t] = W[(long)o * 2 * d + d + c] - W[(long)o * 2 * d + c];
    }
}

// out[p, o] = max_k lrelu(u[nbr, o] + v[p, o])
__global__ void gather_max_kernel(const float* __restrict__ uv,
                                  const int* __restrict__ idx,
                                  float* __restrict__ outp, int outc)
{
    int p = blockIdx.x;
    int b = p >> 10;
    int o = threadIdx.x;
    if (o >= outc) return;
    int ldu = 2 * outc;
    float vi = uv[(long)p * ldu + outc + o];
    const int* ip = idx + (long)p * KNNK;
    float m = -__builtin_huge_valf();
    #pragma unroll 4
    for (int kk = 0; kk < KNNK; kk++) {
        int j = ip[kk];
        float t = uv[((long)(b << 10) + j) * ldu + o] + vi;
        t = (t >= 0.f) ? t : 0.2f * t;
        m = fmaxf(m, t);
    }
    outp[(long)p * CATC + o] = m;
}

__global__ void zenc_init_kernel(unsigned int* __restrict__ zenc)
{
    int t = blockIdx.x * blockDim.x + threadIdx.x;
    if (t < BB * 1024) zenc[t] = 0u;
}

__global__ void zenc_decode_kernel(const unsigned int* __restrict__ zenc,
                                   float* __restrict__ z)
{
    int t = blockIdx.x * blockDim.x + threadIdx.x;
    if (t >= BB * 1024) return;
    int b = t >> 10, o = t & 1023;
    float m = ord_decode(zenc[t]);
    m = (m >= 0.f) ? m : 0.2f * m;
    z[b * 1088 + o] = m;
}

// Small FC
__global__ void fc_kernel(const float* __restrict__ A, int lda,
                          const float* __restrict__ W,
                          const float* __restrict__ bias,
                          float* __restrict__ C, int ldc,
                          int Bn, int O, int Kd, int relu)
{
    int t = blockIdx.x * blockDim.x + threadIdx.x;
    if (t >= Bn * O) return;
    int b = t / O, o = t - b * O;
    const float* a = A + (long)b * lda;
    const float* w = W + (long)o * Kd;
    float s0 = 0.f, s1 = 0.f, s2 = 0.f, s3 = 0.f;
    int k = 0;
    for (; k + 3 < Kd; k += 4) {
        s0 = fmaf(a[k],     w[k],     s0);
        s1 = fmaf(a[k + 1], w[k + 1], s1);
        s2 = fmaf(a[k + 2], w[k + 2], s2);
        s3 = fmaf(a[k + 3], w[k + 3], s3);
    }
    for (; k < Kd; k++) s0 = fmaf(a[k], w[k], s0);
    float s = (s0 + s1) + (s2 + s3) + (bias ? bias[o] : 0.f);
    if (relu) s = (s >= 0.f) ? s : 0.2f * s;
    C[(long)b * ldc + o] = s;
}

// ---------------------------------------------------------------------------
static void run_layer(const float* feat, int lda, int d, int outc,
                      const float* W, float* catOut,
                      float* G, float* xx, int* idxp, float* Wuv, float* uv)
{
    xx_kernel<<<(BB * NN + 255) / 256, 256>>>(feat, lda, d, xx);

    dim3 gG(NN / 128, NN / 128, BB);
    mma_gemm<0><<<gG, 256, SMEM_MMA>>>(feat, feat, G, nullptr, d, lda, lda, NN,
                                       (long)NN * lda, (long)NN * lda,
                                       (long)NN * NN);

    topk_kernel<<<BB * NN / 8, 256>>>(G, xx, idxp);

    int nw = 2 * outc * d;
    wuv_kernel<<<(nw + 255) / 256, 256>>>(W, Wuv, outc, d);

    dim3 gu((2 * outc) / 128, (BB * NN) / 128, 1);
    mma_gemm<0><<<gu, 256, SMEM_MMA>>>(feat, Wuv, uv, nullptr, d, lda, d,
                                       2 * outc, 0, 0, 0);

    gather_max_kernel<<<BB * NN, outc>>>(uv, idxp, catOut, outc);
}

extern "C" void kernel_launch(void* const* d_in, const int* in_sizes, int n_in,
                              void* d_out, int out_size)
{
    const float* x   = (const float*)d_in[0];
    const float* y   = (const float*)d_in[1];
    const float* W0  = (const float*)d_in[2];
    const float* W1  = (const float*)d_in[3];
    const float* W2  = (const float*)d_in[4];
    const float* W3  = (const float*)d_in[5];
    const float* W4  = (const float*)d_in[6];
    const float* L0  = (const float*)d_in[7];
    const float* L1  = (const float*)d_in[8];
    const float* L2w = (const float*)d_in[9];
    const float* L2b = (const float*)d_in[10];
    const float* F0w = (const float*)d_in[11];
    const float* F0b = (const float*)d_in[12];
    const float* F1w = (const float*)d_in[13];
    const float* F1b = (const float*)d_in[14];
    float* out = (float*)d_out;

    cudaFuncSetAttribute(mma_gemm<0>,
                         cudaFuncAttributeMaxDynamicSharedMemorySize, SMEM_MMA);
    cudaFuncSetAttribute(mma_gemm<1>,
                         cudaFuncAttributeMaxDynamicSharedMemorySize, SMEM_MMA);

    float *G, *cat, *uv, *xx, *Wuv, *z, *ye0, *z1, *z2;
    unsigned int* zenc;
    int* idxp;
    cudaGetSymbolAddress((void**)&G,    g_G);
    cudaGetSymbolAddress((void**)&cat,  g_cat);
    cudaGetSymbolAddress((void**)&uv,   g_uv);
    cudaGetSymbolAddress((void**)&xx,   g_xx);
    cudaGetSymbolAddress((void**)&Wuv,  g_Wuv);
    cudaGetSymbolAddress((void**)&z,    g_z);
    cudaGetSymbolAddress((void**)&ye0,  g_ye0);
    cudaGetSymbolAddress((void**)&z1,   g_z1);
    cudaGetSymbolAddress((void**)&z2,   g_z2);
    cudaGetSymbolAddress((void**)&zenc, g_zenc);
    cudaGetSymbolAddress((void**)&idxp, g_idx);

    run_layer(x,         6,   6,   64,  W0, cat + 0,   G, xx, idxp, Wuv, uv);
    run_layer(cat + 0,   512, 64,  64,  W1, cat + 64,  G, xx, idxp, Wuv, uv);
    run_layer(cat + 64,  512, 64,  128, W2, cat + 128, G, xx, idxp, Wuv, uv);
    run_layer(cat + 128, 512, 128, 256, W3, cat + 256, G, xx, idxp, Wuv, uv);

    // W4 GEMM (tensor) fused with column max
    zenc_init_kernel<<<(BB * 1024 + 255) / 256, 256>>>(zenc);
    dim3 g4(1024 / 128, (BB * NN) / 128, 1);
    mma_gemm<1><<<g4, 256, SMEM_MMA>>>(cat, W4, nullptr, zenc, 512, 512, 512, 0,
                                       0, 0, 0);
    zenc_decode_kernel<<<(BB * 1024 + 255) / 256, 256>>>(zenc, z);

    fc_kernel<<<1, 256>>>(y, 16, F0w, F0b, ye0, 16, BB, 16, 16, 1);
    fc_kernel<<<(BB * 64 + 255) / 256, 256>>>(ye0, 16, F1w, F1b, z + 1024, 1088,
                                              BB, 64, 16, 1);

    fc_kernel<<<(BB * 512 + 255) / 256, 256>>>(z, 1088, L0, nullptr, z1, 512,
                                               BB, 512, 1088, 1);
    fc_kernel<<<(BB * 256 + 255) / 256, 256>>>(z1, 512, L1, nullptr, z2, 256,
                                               BB, 256, 512, 1);
    fc_kernel<<<1, 16>>>(z2, 256, L2w, L2b, out, 1, BB, 1, 256, 0);
}